// round 2
// baseline (speedup 1.0000x reference)
#include <cuda_runtime.h>

#define BB  2
#define LL  1024
#define DD  256
#define UU  32
#define QPB 8          // queries per CTA
#define KC  64         // k-chunk staged in smem for pass 1

// scratch (no cudaMalloc allowed): q and t = k + bh, each [B, L, U]
__device__ float g_q[BB*LL*UU];
__device__ float g_t[BB*LL*UU];

// Accurate-enough tanh: 1 - 2/(e^{2x}+1). Robust at +/-inf of exp.
__device__ __forceinline__ float fast_tanh(float x) {
    float e = __expf(2.0f * x);
    return 1.0f - __fdividef(2.0f, e + 1.0f);
}

// ---------------------------------------------------------------------------
// Kernel A: q[b,l,u] = inputs[b,l,:] . Wt[:,u] ; t[b,l,u] = inputs[b,l,:] . Wx[u,:] + bh[u]
// Block = 256 threads = 8 rows x 32 units.
// ---------------------------------------------------------------------------
__global__ __launch_bounds__(256) void proj_kernel(
    const float* __restrict__ inputs, const float* __restrict__ Wt,
    const float* __restrict__ Wx, const float* __restrict__ bh)
{
    __shared__ float s_in[8][DD];
    const int base_row = blockIdx.x * 8;
    for (int i = threadIdx.x; i < 8 * DD; i += 256) {
        s_in[i >> 8][i & 255] = inputs[base_row * DD + i];
    }
    __syncthreads();

    const int lr = threadIdx.x >> 5;   // local row 0..7
    const int u  = threadIdx.x & 31;   // unit 0..31
    float accq = 0.0f, acck = 0.0f;
    const float* wx_row = Wx + u * DD;
    #pragma unroll 8
    for (int d = 0; d < DD; d++) {
        float x = s_in[lr][d];
        accq = fmaf(x, Wt[d * UU + u], accq);   // coalesced over u
        acck = fmaf(x, __ldg(wx_row + d), acck); // Wx row, L1-resident (32KB)
    }
    const int row = base_row + lr;
    g_q[row * UU + u] = accq;
    g_t[row * UU + u] = acck + bh[u];
}

// ---------------------------------------------------------------------------
// Kernel B: fused alpha -> softmax -> P @ V.
// Grid = B*L/QPB CTAs, 256 threads. One warp per query for pass 1/2.
// Pass 3: 4 k-slices x 64 float4-columns register tiling (8q x 4d per thread).
// ---------------------------------------------------------------------------
__global__ __launch_bounds__(256) void attn_kernel(
    const float* __restrict__ inputs, const float* __restrict__ Wa,
    const float* __restrict__ ba, float* __restrict__ out)
{
    __shared__ float s_t[KC][UU + 1];     // 8448 B, +1 pad -> conflict-free
    __shared__ float s_alpha[QPB][LL];    // 32768 B (alpha, then exp(alpha-max))
    __shared__ float s_q[QPB][UU];        // 1024 B
    __shared__ float s_wa[UU];
    __shared__ float s_inv[QPB];

    const int b    = blockIdx.x / (LL / QPB);
    const int q0   = (blockIdx.x % (LL / QPB)) * QPB;
    const int tid  = threadIdx.x;
    const int warp = tid >> 5;
    const int lane = tid & 31;

    // 256 threads == QPB*UU: one element each
    s_q[warp][lane] = g_q[((size_t)b * LL + q0 + warp) * UU + lane];
    if (tid < UU) s_wa[tid] = Wa[tid];   // Wa is (U,1)
    const float bav = ba[0];
    __syncthreads();

    // ---------------- Pass 1: alpha[q][k] for this CTA's 8 queries -------------
    float lmax = -1e30f;
    for (int c0 = 0; c0 < LL; c0 += KC) {
        for (int i = tid; i < KC * UU; i += 256) {
            int kk = i >> 5, uu = i & 31;
            s_t[kk][uu] = g_t[((size_t)b * LL + c0 + kk) * UU + uu];
        }
        __syncthreads();
        #pragma unroll
        for (int j = 0; j < KC / 32; j++) {
            const int kl = j * 32 + lane;
            float acc = bav;
            #pragma unroll
            for (int uu = 0; uu < UU; uu++) {
                float x = s_q[warp][uu] + s_t[kl][uu];   // s_t conflict-free (33-stride)
                acc = fmaf(fast_tanh(x), s_wa[uu], acc);
            }
            s_alpha[warp][c0 + kl] = acc;
            lmax = fmaxf(lmax, acc);
        }
        __syncthreads();   // protect s_t for next chunk
    }

    // ---------------- Pass 2: stable softmax (per warp = per query) ------------
    #pragma unroll
    for (int off = 16; off; off >>= 1)
        lmax = fmaxf(lmax, __shfl_xor_sync(0xffffffffu, lmax, off));
    float lsum = 0.0f;
    for (int kl = lane; kl < LL; kl += 32) {
        float p = __expf(s_alpha[warp][kl] - lmax);
        s_alpha[warp][kl] = p;
        lsum += p;
    }
    #pragma unroll
    for (int off = 16; off; off >>= 1)
        lsum += __shfl_xor_sync(0xffffffffu, lsum, off);
    if (lane == 0) s_inv[warp] = 1.0f / lsum;
    __syncthreads();   // all p + s_inv visible to all threads

    // ---------------- Pass 3: C[q][d] = sum_k p[q][k] * V[k][d] ---------------
    // thread = (ks, dcol): ks = k-slice 0..3 (uniform per warp), dcol = float4 col 0..63
    const int ks   = tid >> 6;
    const int dcol = tid & 63;
    const float4* inb = (const float4*)(inputs + (size_t)b * LL * DD);

    float4 acc[QPB];
    #pragma unroll
    for (int qq = 0; qq < QPB; qq++) acc[qq] = make_float4(0.f, 0.f, 0.f, 0.f);

    for (int k = ks; k < LL; k += 4) {
        const float4 v = inb[k * (DD / 4) + dcol];      // coalesced 512B / warp
        #pragma unroll
        for (int qq = 0; qq < QPB; qq++) {
            const float p = s_alpha[qq][k];             // warp-uniform broadcast LDS
            acc[qq].x = fmaf(p, v.x, acc[qq].x);
            acc[qq].y = fmaf(p, v.y, acc[qq].y);
            acc[qq].z = fmaf(p, v.z, acc[qq].z);
            acc[qq].w = fmaf(p, v.w, acc[qq].w);
        }
    }

    // serial-chain reduction over ks slices 3 -> 2 -> 1 -> 0 through s_t scratch
    float4* s_part = (float4*)&s_t[0][0];   // 8448 B >= 64*8*16 B per round
    __syncthreads();
    #pragma unroll
    for (int src = 3; src >= 1; src--) {
        if (ks == src) {
            #pragma unroll
            for (int qq = 0; qq < QPB; qq++) s_part[dcol * QPB + qq] = acc[qq];
        }
        __syncthreads();
        if (ks == src - 1) {
            #pragma unroll
            for (int qq = 0; qq < QPB; qq++) {
                float4 t = s_part[dcol * QPB + qq];
                acc[qq].x += t.x; acc[qq].y += t.y; acc[qq].z += t.z; acc[qq].w += t.w;
            }
        }
        __syncthreads();
    }

    if (ks == 0) {
        float4* outb = (float4*)(out + ((size_t)b * LL + q0) * DD);
        #pragma unroll
        for (int qq = 0; qq < QPB; qq++) {
            const float inv = s_inv[qq];
            float4 r = acc[qq];
            r.x *= inv; r.y *= inv; r.z *= inv; r.w *= inv;
            outb[qq * (DD / 4) + dcol] = r;   // coalesced
        }
    }
}

// ---------------------------------------------------------------------------
extern "C" void kernel_launch(void* const* d_in, const int* in_sizes, int n_in,
                              void* d_out, int out_size) {
    const float* inputs = (const float*)d_in[0];  // [B, L, D]
    const float* Wt     = (const float*)d_in[1];  // [D, U]
    const float* Wx     = (const float*)d_in[2];  // [U, D]
    const float* bh     = (const float*)d_in[3];  // [U]
    const float* Wa     = (const float*)d_in[4];  // [U, 1]
    const float* ba     = (const float*)d_in[5];  // [1]
    float* out = (float*)d_out;                   // [B, L, D] fp32

    proj_kernel<<<BB * LL / 8, 256>>>(inputs, Wt, Wx, bh);
    attn_kernel<<<BB * LL / QPB, 256>>>(inputs, Wa, ba, out);
}

// round 3
// speedup vs baseline: 2.0752x; 2.0752x over previous
#include <cuda_runtime.h>

#define BB  2
#define LL  1024
#define DD  256
#define UU  32
#define QPB 8          // queries per CTA
#define KC  64         // k-chunk staged in smem for pass 1

// scratch (no cudaMalloc allowed): q and t = k + bh, each [B, L, U]
__device__ float g_q[BB*LL*UU];
__device__ float g_t[BB*LL*UU];

// HW tanh: MUFU.TANH, abs err ~2^-10.7 — well within the 1e-3 output gate.
__device__ __forceinline__ float htanh(float x) {
    float y;
    asm("tanh.approx.f32 %0, %1;" : "=f"(y) : "f"(x));
    return y;
}

// ---------------------------------------------------------------------------
// Kernel A: q = X @ Wt ; t = X @ Wx^T + bh.  8 rows per CTA, warp = row,
// lane = unit. Weights staged once in smem as [d4][u] float4 packs (64KB dyn).
// ---------------------------------------------------------------------------
__global__ __launch_bounds__(256) void proj_kernel(
    const float* __restrict__ inputs, const float* __restrict__ Wt,
    const float* __restrict__ Wx, const float* __restrict__ bh)
{
    extern __shared__ float4 s_w[];            // [0:2048) Wt4, [2048:4096) Wx4
    float4* s_wt4 = s_w;
    float4* s_wx4 = s_w + 2048;

    // Stage weights: s_wt4[d4*32+u] = Wt[4d4..4d4+3][u]; s_wx4 = Wx[u][4d4..]
    for (int i = threadIdx.x; i < 64 * 32; i += 256) {
        const int d4 = i >> 5, u = i & 31;
        s_wt4[i] = make_float4(Wt[(4*d4+0)*UU + u], Wt[(4*d4+1)*UU + u],
                               Wt[(4*d4+2)*UU + u], Wt[(4*d4+3)*UU + u]);
        s_wx4[i] = ((const float4*)(Wx + u * DD))[d4];
    }
    __syncthreads();

    const int warp = threadIdx.x >> 5;     // local row
    const int u    = threadIdx.x & 31;
    const int row  = blockIdx.x * 8 + warp;
    const float4* xr = (const float4*)(inputs + (size_t)row * DD);

    float accq = 0.0f, acck = 0.0f;
    #pragma unroll 8
    for (int d4 = 0; d4 < 64; d4++) {
        const float4 x  = xr[d4];               // warp-uniform, L1/L2 hot
        const float4 wt = s_wt4[d4 * 32 + u];   // conflict-free LDS.128
        const float4 wx = s_wx4[d4 * 32 + u];
        accq = fmaf(x.x, wt.x, accq); accq = fmaf(x.y, wt.y, accq);
        accq = fmaf(x.z, wt.z, accq); accq = fmaf(x.w, wt.w, accq);
        acck = fmaf(x.x, wx.x, acck); acck = fmaf(x.y, wx.y, acck);
        acck = fmaf(x.z, wx.z, acck); acck = fmaf(x.w, wx.w, acck);
    }
    g_q[row * UU + u] = accq;
    g_t[row * UU + u] = acck + bh[u];
}

// ---------------------------------------------------------------------------
// Kernel B: fused alpha -> softmax -> P @ V.
// Grid = B*L/QPB CTAs, 256 threads. Warp = query for pass 1/2.
// Pass 3: 4 contiguous k-slices x 64 float4 d-columns; p via broadcast LDS.128.
// ---------------------------------------------------------------------------
__global__ __launch_bounds__(256) void attn_kernel(
    const float* __restrict__ inputs, const float* __restrict__ Wa,
    const float* __restrict__ ba, float* __restrict__ out)
{
    __shared__ float s_t[KC][UU + 4];     // 9216 B, float4-friendly pad
    __shared__ float s_alpha[QPB][LL];    // 32768 B (alpha, then p)
    __shared__ float s_q[QPB][UU];        // 1024 B
    __shared__ float s_wa[UU];
    __shared__ float s_inv[QPB];

    const int b    = blockIdx.x / (LL / QPB);
    const int q0   = (blockIdx.x % (LL / QPB)) * QPB;
    const int tid  = threadIdx.x;
    const int warp = tid >> 5;
    const int lane = tid & 31;

    s_q[warp][lane] = g_q[((size_t)b * LL + q0 + warp) * UU + lane];
    if (tid < UU) s_wa[tid] = Wa[tid];
    const float bav = ba[0];
    __syncthreads();

    // ---------------- Pass 1: alpha[q][k], MUFU.TANH, float4 LDS --------------
    float lmax = -1e30f;
    for (int c0 = 0; c0 < LL; c0 += KC) {
        const float4* gt4 = (const float4*)(g_t + ((size_t)b * LL + c0) * UU);
        for (int i = tid; i < KC * 8; i += 256) {
            const int kk = i >> 3, u4 = i & 7;
            ((float4*)&s_t[kk][0])[u4] = gt4[i];
        }
        __syncthreads();
        const float4* q4  = (const float4*)&s_q[warp][0];
        const float4* wa4 = (const float4*)&s_wa[0];
        #pragma unroll
        for (int j = 0; j < KC / 32; j++) {
            const int kl = j * 32 + lane;
            const float4* t4 = (const float4*)&s_t[kl][0];
            float acc = bav;
            #pragma unroll
            for (int u4 = 0; u4 < 8; u4++) {
                const float4 qv = q4[u4];      // broadcast
                const float4 tv = t4[u4];      // conflict-free (36f stride)
                const float4 wv = wa4[u4];     // broadcast
                acc = fmaf(htanh(qv.x + tv.x), wv.x, acc);
                acc = fmaf(htanh(qv.y + tv.y), wv.y, acc);
                acc = fmaf(htanh(qv.z + tv.z), wv.z, acc);
                acc = fmaf(htanh(qv.w + tv.w), wv.w, acc);
            }
            s_alpha[warp][c0 + kl] = acc;
            lmax = fmaxf(lmax, acc);
        }
        __syncthreads();
    }

    // ---------------- Pass 2: stable softmax (warp = query) -------------------
    #pragma unroll
    for (int off = 16; off; off >>= 1)
        lmax = fmaxf(lmax, __shfl_xor_sync(0xffffffffu, lmax, off));
    float lsum = 0.0f;
    for (int kl = lane; kl < LL; kl += 32) {
        float p = __expf(s_alpha[warp][kl] - lmax);
        s_alpha[warp][kl] = p;
        lsum += p;
    }
    #pragma unroll
    for (int off = 16; off; off >>= 1)
        lsum += __shfl_xor_sync(0xffffffffu, lsum, off);
    if (lane == 0) s_inv[warp] = 1.0f / lsum;
    __syncthreads();

    // ---------------- Pass 3: C[q][d] = sum_k p[q][k] * V[k][d] ---------------
    // ks = contiguous k-slice (256 keys), dcol = float4 column. p loads are
    // warp-uniform broadcast LDS.128; 128 FMA per 4-k step (91% density).
    const int ks   = tid >> 6;
    const int dcol = tid & 63;
    const float4* inb = (const float4*)(inputs + (size_t)b * LL * DD);

    float4 acc[QPB];
    #pragma unroll
    for (int qq = 0; qq < QPB; qq++) acc[qq] = make_float4(0.f, 0.f, 0.f, 0.f);

    const int kbeg = ks * (LL / 4);
    #pragma unroll 1
    for (int k0 = kbeg; k0 < kbeg + LL / 4; k0 += 4) {
        const float4 v0 = inb[(k0 + 0) * (DD / 4) + dcol];
        const float4 v1 = inb[(k0 + 1) * (DD / 4) + dcol];
        const float4 v2 = inb[(k0 + 2) * (DD / 4) + dcol];
        const float4 v3 = inb[(k0 + 3) * (DD / 4) + dcol];
        #pragma unroll
        for (int qq = 0; qq < QPB; qq++) {
            const float4 p4 = *(const float4*)&s_alpha[qq][k0];  // broadcast
            acc[qq].x = fmaf(p4.x, v0.x, acc[qq].x);
            acc[qq].y = fmaf(p4.x, v0.y, acc[qq].y);
            acc[qq].z = fmaf(p4.x, v0.z, acc[qq].z);
            acc[qq].w = fmaf(p4.x, v0.w, acc[qq].w);
            acc[qq].x = fmaf(p4.y, v1.x, acc[qq].x);
            acc[qq].y = fmaf(p4.y, v1.y, acc[qq].y);
            acc[qq].z = fmaf(p4.y, v1.z, acc[qq].z);
            acc[qq].w = fmaf(p4.y, v1.w, acc[qq].w);
            acc[qq].x = fmaf(p4.z, v2.x, acc[qq].x);
            acc[qq].y = fmaf(p4.z, v2.y, acc[qq].y);
            acc[qq].z = fmaf(p4.z, v2.z, acc[qq].z);
            acc[qq].w = fmaf(p4.z, v2.w, acc[qq].w);
            acc[qq].x = fmaf(p4.w, v3.x, acc[qq].x);
            acc[qq].y = fmaf(p4.w, v3.y, acc[qq].y);
            acc[qq].z = fmaf(p4.w, v3.z, acc[qq].z);
            acc[qq].w = fmaf(p4.w, v3.w, acc[qq].w);
        }
    }

    // serial-chain reduction over ks slices 3 -> 2 -> 1 -> 0 through s_t scratch
    float4* s_part = (float4*)&s_t[0][0];   // 9216 B >= 8192 B per round
    __syncthreads();
    #pragma unroll
    for (int src = 3; src >= 1; src--) {
        if (ks == src) {
            #pragma unroll
            for (int qq = 0; qq < QPB; qq++) s_part[dcol * QPB + qq] = acc[qq];
        }
        __syncthreads();
        if (ks == src - 1) {
            #pragma unroll
            for (int qq = 0; qq < QPB; qq++) {
                float4 t = s_part[dcol * QPB + qq];
                acc[qq].x += t.x; acc[qq].y += t.y; acc[qq].z += t.z; acc[qq].w += t.w;
            }
        }
        __syncthreads();
    }

    if (ks == 0) {
        float4* outb = (float4*)(out + ((size_t)b * LL + q0) * DD);
        #pragma unroll
        for (int qq = 0; qq < QPB; qq++) {
            const float inv = s_inv[qq];
            float4 r = acc[qq];
            r.x *= inv; r.y *= inv; r.z *= inv; r.w *= inv;
            outb[qq * (DD / 4) + dcol] = r;
        }
    }
}

// ---------------------------------------------------------------------------
extern "C" void kernel_launch(void* const* d_in, const int* in_sizes, int n_in,
                              void* d_out, int out_size) {
    const float* inputs = (const float*)d_in[0];  // [B, L, D]
    const float* Wt     = (const float*)d_in[1];  // [D, U]
    const float* Wx     = (const float*)d_in[2];  // [U, D]
    const float* bh     = (const float*)d_in[3];  // [U]
    const float* Wa     = (const float*)d_in[4];  // [U, 1]
    const float* ba     = (const float*)d_in[5];  // [1]
    float* out = (float*)d_out;                   // [B, L, D] fp32

    cudaFuncSetAttribute(proj_kernel,
                         cudaFuncAttributeMaxDynamicSharedMemorySize, 65536);
    proj_kernel<<<BB * LL / 8, 256, 65536>>>(inputs, Wt, Wx, bh);
    attn_kernel<<<BB * LL / QPB, 256>>>(inputs, Wa, ba, out);
}

// round 5
// speedup vs baseline: 2.3736x; 1.1438x over previous
#include <cuda_runtime.h>
#include <cuda_bf16.h>
#include <cstdint>

#define BB  2
#define LL  1024
#define DD  256
#define UU  32
#define QPB 8
#define KC  64
#define KCH 64       // k-chunk for pv gemm
#define PITCH 72     // smem row pitch in bf16 (144B: conflict-free ldmatrix)

// ---- device scratch (no allocs allowed) ----
__device__ __align__(16) float g_q[BB*LL*UU];
__device__ __align__(16) float g_t[BB*LL*UU];
__device__ __align__(16) __nv_bfloat16 g_ph[BB*LL*LL];   // P hi (normalized)
__device__ __align__(16) __nv_bfloat16 g_pl[BB*LL*LL];   // P lo
__device__ __align__(16) __nv_bfloat16 g_vh[BB*LL*DD];   // V hi  [b][k][d]
__device__ __align__(16) __nv_bfloat16 g_vl[BB*LL*DD];   // V lo

__device__ __forceinline__ float htanh(float x) {
    float y; asm("tanh.approx.f32 %0, %1;" : "=f"(y) : "f"(x)); return y;
}
__device__ __forceinline__ uint32_t smem_u32(const void* p) {
    uint32_t a;
    asm("{ .reg .u64 t; cvta.to.shared.u64 t, %1; cvt.u32.u64 %0, t; }" : "=r"(a) : "l"(p));
    return a;
}
__device__ __forceinline__ void ldsm4(uint32_t* r, uint32_t addr) {
    asm volatile("ldmatrix.sync.aligned.m8n8.x4.shared.b16 {%0,%1,%2,%3}, [%4];"
        : "=r"(r[0]), "=r"(r[1]), "=r"(r[2]), "=r"(r[3]) : "r"(addr));
}
__device__ __forceinline__ void ldsm2t(uint32_t* r, uint32_t addr) {
    asm volatile("ldmatrix.sync.aligned.m8n8.x2.trans.shared.b16 {%0,%1}, [%2];"
        : "=r"(r[0]), "=r"(r[1]) : "r"(addr));
}
__device__ __forceinline__ void mma16816(float* c, const uint32_t* a, const uint32_t* b) {
    asm volatile("mma.sync.aligned.m16n8k16.row.col.f32.bf16.bf16.f32 "
        "{%0,%1,%2,%3}, {%4,%5,%6,%7}, {%8,%9}, {%0,%1,%2,%3};"
        : "+f"(c[0]), "+f"(c[1]), "+f"(c[2]), "+f"(c[3])
        : "r"(a[0]), "r"(a[1]), "r"(a[2]), "r"(a[3]), "r"(b[0]), "r"(b[1]));
}

// ===========================================================================
// Kernel A: q = X @ Wt ; t = X @ Wx^T + bh ; also split V=X into bf16 hi/lo.
// ===========================================================================
__global__ __launch_bounds__(256) void proj_kernel(
    const float* __restrict__ inputs, const float* __restrict__ Wt,
    const float* __restrict__ Wx, const float* __restrict__ bh)
{
    extern __shared__ float4 s_w[];
    float4* s_wt4 = s_w;
    float4* s_wx4 = s_w + 2048;
    for (int i = threadIdx.x; i < 64 * 32; i += 256) {
        const int d4 = i >> 5, u = i & 31;
        s_wt4[i] = make_float4(Wt[(4*d4+0)*UU + u], Wt[(4*d4+1)*UU + u],
                               Wt[(4*d4+2)*UU + u], Wt[(4*d4+3)*UU + u]);
        s_wx4[i] = ((const float4*)(Wx + u * DD))[d4];
    }
    __syncthreads();

    const int warp = threadIdx.x >> 5;
    const int u    = threadIdx.x & 31;   // lane
    const int row  = blockIdx.x * 8 + warp;
    const float4* xr = (const float4*)(inputs + (size_t)row * DD);

    // V hi/lo split: this thread handles d = u*8 .. u*8+7 of its row
    {
        const float4 xa = xr[u * 2], xb = xr[u * 2 + 1];
        const float v[8] = {xa.x, xa.y, xa.z, xa.w, xb.x, xb.y, xb.z, xb.w};
        __nv_bfloat16 hbuf[8], lbuf[8];
        #pragma unroll
        for (int j = 0; j < 8; j++) {
            const __nv_bfloat16 h = __float2bfloat16(v[j]);
            hbuf[j] = h;
            lbuf[j] = __float2bfloat16(v[j] - __bfloat162float(h));
        }
        *(uint4*)(g_vh + (size_t)row * DD + u * 8) = *(const uint4*)hbuf;
        *(uint4*)(g_vl + (size_t)row * DD + u * 8) = *(const uint4*)lbuf;
    }

    float accq = 0.0f, acck = 0.0f;
    #pragma unroll 8
    for (int d4 = 0; d4 < 64; d4++) {
        const float4 x  = xr[d4];
        const float4 wt = s_wt4[d4 * 32 + u];
        const float4 wx = s_wx4[d4 * 32 + u];
        accq = fmaf(x.x, wt.x, accq); accq = fmaf(x.y, wt.y, accq);
        accq = fmaf(x.z, wt.z, accq); accq = fmaf(x.w, wt.w, accq);
        acck = fmaf(x.x, wx.x, acck); acck = fmaf(x.y, wx.y, acck);
        acck = fmaf(x.z, wx.z, acck); acck = fmaf(x.w, wx.w, acck);
    }
    g_q[row * UU + u] = accq;
    g_t[row * UU + u] = acck + bh[u];
}

// ===========================================================================
// Kernel B: alpha = tanh(q+t)·Wa + ba -> softmax -> store normalized P hi/lo
// ===========================================================================
__global__ __launch_bounds__(256) void alpha_kernel(
    const float* __restrict__ Wa, const float* __restrict__ ba)
{
    __shared__ float s_t[KC][UU + 4];
    __shared__ float s_alpha[QPB][LL];
    __shared__ float s_q[QPB][UU];
    __shared__ float s_wa[UU];

    const int b    = blockIdx.x / (LL / QPB);
    const int q0   = (blockIdx.x % (LL / QPB)) * QPB;
    const int tid  = threadIdx.x;
    const int warp = tid >> 5;
    const int lane = tid & 31;

    s_q[warp][lane] = g_q[((size_t)b * LL + q0 + warp) * UU + lane];
    if (tid < UU) s_wa[tid] = Wa[tid];
    const float bav = ba[0];
    __syncthreads();

    float lmax = -1e30f;
    for (int c0 = 0; c0 < LL; c0 += KC) {
        const float4* gt4 = (const float4*)(g_t + ((size_t)b * LL + c0) * UU);
        for (int i = tid; i < KC * 8; i += 256)
            ((float4*)&s_t[i >> 3][0])[i & 7] = gt4[i];
        __syncthreads();
        const float4* q4  = (const float4*)&s_q[warp][0];
        const float4* wa4 = (const float4*)&s_wa[0];
        #pragma unroll
        for (int j = 0; j < KC / 32; j++) {
            const int kl = j * 32 + lane;
            const float4* t4 = (const float4*)&s_t[kl][0];
            float a0 = 0.f, a1 = 0.f, a2 = 0.f, a3 = 0.f;  // 4 chains
            #pragma unroll
            for (int u4 = 0; u4 < 8; u4++) {
                const float4 qv = q4[u4];
                const float4 tv = t4[u4];
                const float4 wv = wa4[u4];
                a0 = fmaf(htanh(qv.x + tv.x), wv.x, a0);
                a1 = fmaf(htanh(qv.y + tv.y), wv.y, a1);
                a2 = fmaf(htanh(qv.z + tv.z), wv.z, a2);
                a3 = fmaf(htanh(qv.w + tv.w), wv.w, a3);
            }
            const float acc = bav + ((a0 + a1) + (a2 + a3));
            s_alpha[warp][c0 + kl] = acc;
            lmax = fmaxf(lmax, acc);
        }
        __syncthreads();
    }

    #pragma unroll
    for (int off = 16; off; off >>= 1)
        lmax = fmaxf(lmax, __shfl_xor_sync(0xffffffffu, lmax, off));
    float lsum = 0.0f;
    for (int kl = lane; kl < LL; kl += 32) {
        float p = __expf(s_alpha[warp][kl] - lmax);
        s_alpha[warp][kl] = p;
        lsum += p;
    }
    #pragma unroll
    for (int off = 16; off; off >>= 1)
        lsum += __shfl_xor_sync(0xffffffffu, lsum, off);
    const float inv = 1.0f / lsum;

    const size_t rowb = ((size_t)b * LL + q0 + warp) * LL;
    for (int kl = lane; kl < LL; kl += 32) {
        const float p = s_alpha[warp][kl] * inv;
        const __nv_bfloat16 hi = __float2bfloat16(p);
        const __nv_bfloat16 lo = __float2bfloat16(p - __bfloat162float(hi));
        g_ph[rowb + kl] = hi;
        g_pl[rowb + kl] = lo;
    }
}

// ===========================================================================
// Kernel C: warp-MMA GEMM  C[64 q x 64 d] tile = P @ V  (split bf16, fp32 acc)
// 8 warps: warp_m (2) x warp_n (4); each warp 32 rows x 16 cols = 2x2 frags.
// ===========================================================================
#define OFF_AH 0
#define OFF_AL (64*PITCH)
#define OFF_BH (2*64*PITCH)
#define OFF_BL (3*64*PITCH)
#define PV_SMEM_BYTES (4*64*PITCH*2)

__global__ __launch_bounds__(256) void pv_kernel(float* __restrict__ out)
{
    extern __shared__ __align__(16) __nv_bfloat16 sm[];
    const int tid    = threadIdx.x;
    const int wid    = tid >> 5;
    const int lane   = tid & 31;
    const int warp_m = wid >> 2;      // 0..1  (32 rows)
    const int warp_n = wid & 3;       // 0..3  (16 cols)
    const int q0g    = blockIdx.x * 64;       // global row in [0, 2048)
    const int b      = q0g >> 10;
    const int n0     = blockIdx.y * 64;
    const uint32_t smb = smem_u32(sm);

    float acc[2][2][4];
    #pragma unroll
    for (int mt = 0; mt < 2; mt++)
        #pragma unroll
        for (int nt = 0; nt < 2; nt++)
            acc[mt][nt][0] = acc[mt][nt][1] = acc[mt][nt][2] = acc[mt][nt][3] = 0.f;

    #pragma unroll 1
    for (int c = 0; c < LL / KCH; c++) {
        const int kc0 = c * KCH;
        // ---- stage A = P tile [64 rows x 64 k], hi+lo planes ----
        #pragma unroll
        for (int it = 0; it < 4; it++) {
            const int idx   = tid + it * 256;       // 0..1023
            const int plane = idx >> 9;
            const int r     = (idx >> 3) & 63;
            const int k8    = (idx & 7) * 8;
            const __nv_bfloat16* src = plane ? g_pl : g_ph;
            const uint4 v = *(const uint4*)(src + (size_t)(q0g + r) * LL + kc0 + k8);
            *(uint4*)(sm + (plane ? OFF_AL : OFF_AH) + r * PITCH + k8) = v;
        }
        // ---- stage B = V tile [64 k x 64 d], hi+lo planes ----
        #pragma unroll
        for (int it = 0; it < 4; it++) {
            const int idx   = tid + it * 256;
            const int plane = idx >> 9;
            const int r     = (idx >> 3) & 63;      // k row
            const int n8    = (idx & 7) * 8;
            const __nv_bfloat16* src = plane ? g_vl : g_vh;
            const uint4 v = *(const uint4*)(src + (size_t)(b * LL + kc0 + r) * DD + n0 + n8);
            *(uint4*)(sm + (plane ? OFF_BL : OFF_BH) + r * PITCH + n8) = v;
        }
        __syncthreads();

        #pragma unroll
        for (int kk = 0; kk < KCH; kk += 16) {
            uint32_t ah[2][4], al[2][4], bh[2][2], bl[2][2];
            #pragma unroll
            for (int mt = 0; mt < 2; mt++) {
                const int row = warp_m * 32 + mt * 16 + (lane & 15);
                const int col = kk + (lane >> 4) * 8;
                ldsm4(ah[mt], smb + (uint32_t)(OFF_AH + row * PITCH + col) * 2);
                ldsm4(al[mt], smb + (uint32_t)(OFF_AL + row * PITCH + col) * 2);
            }
            #pragma unroll
            for (int nt = 0; nt < 2; nt++) {
                const int krow = kk + (lane & 15);
                const int col  = warp_n * 16 + nt * 8;
                ldsm2t(bh[nt], smb + (uint32_t)(OFF_BH + krow * PITCH + col) * 2);
                ldsm2t(bl[nt], smb + (uint32_t)(OFF_BL + krow * PITCH + col) * 2);
            }
            #pragma unroll
            for (int mt = 0; mt < 2; mt++)
                #pragma unroll
                for (int nt = 0; nt < 2; nt++) {
                    mma16816(acc[mt][nt], ah[mt], bh[nt]);   // Ph*Vh
                    mma16816(acc[mt][nt], ah[mt], bl[nt]);   // Ph*Vl
                    mma16816(acc[mt][nt], al[mt], bh[nt]);   // Pl*Vh
                }
        }
        __syncthreads();
    }

    // ---- epilogue: fragment -> gmem (P already normalized) ----
    #pragma unroll
    for (int mt = 0; mt < 2; mt++)
        #pragma unroll
        for (int nt = 0; nt < 2; nt++) {
            const int row = q0g + warp_m * 32 + mt * 16 + (lane >> 2);
            const int col = n0 + warp_n * 16 + nt * 8 + (lane & 3) * 2;
            float* o = out + (size_t)row * DD + col;
            o[0] = acc[mt][nt][0];
            o[1] = acc[mt][nt][1];
            o[8 * DD + 0] = acc[mt][nt][2];
            o[8 * DD + 1] = acc[mt][nt][3];
        }
}

// ===========================================================================
extern "C" void kernel_launch(void* const* d_in, const int* in_sizes, int n_in,
                              void* d_out, int out_size) {
    const float* inputs = (const float*)d_in[0];
    const float* Wt     = (const float*)d_in[1];
    const float* Wx     = (const float*)d_in[2];
    const float* bh     = (const float*)d_in[3];
    const float* Wa     = (const float*)d_in[4];
    const float* ba     = (const float*)d_in[5];
    float* out = (float*)d_out;

    cudaFuncSetAttribute(proj_kernel, cudaFuncAttributeMaxDynamicSharedMemorySize, 65536);

    proj_kernel<<<BB * LL / 8, 256, 65536>>>(inputs, Wt, Wx, bh);
    alpha_kernel<<<BB * LL / QPB, 256>>>(Wa, ba);
    pv_kernel<<<dim3(BB * LL / 64, DD / 64), 256, PV_SMEM_BYTES>>>(out);
}

// round 7
// speedup vs baseline: 2.4567x; 1.0350x over previous
#include <cuda_runtime.h>
#include <cuda_bf16.h>
#include <cstdint>

#define BB  2
#define LL  1024
#define DD  256
#define UU  32
#define QPB 8
#define KC  64
#define KCH 64       // k-chunk for pv gemm
#define PITCH 72     // smem row pitch in bf16 (144B: conflict-free ldmatrix)

// ---- device scratch (no allocs allowed) ----
__device__ __align__(16) float g_q[BB*LL*UU];
__device__ __align__(16) float g_t[BB*LL*UU];
__device__ __align__(16) __nv_bfloat16 g_ph[BB*LL*LL];   // P hi (normalized)
__device__ __align__(16) __nv_bfloat16 g_pl[BB*LL*LL];   // P lo
__device__ __align__(16) __nv_bfloat16 g_vh[BB*LL*DD];   // V hi  [b][k][d]
__device__ __align__(16) __nv_bfloat16 g_vl[BB*LL*DD];   // V lo

__device__ __forceinline__ float htanh(float x) {
    float y; asm("tanh.approx.f32 %0, %1;" : "=f"(y) : "f"(x)); return y;
}
__device__ __forceinline__ uint32_t smem_u32(const void* p) {
    uint32_t a;
    asm("{ .reg .u64 t; cvta.to.shared.u64 t, %1; cvt.u32.u64 %0, t; }" : "=r"(a) : "l"(p));
    return a;
}
__device__ __forceinline__ void ldsm4(uint32_t* r, uint32_t addr) {
    asm volatile("ldmatrix.sync.aligned.m8n8.x4.shared.b16 {%0,%1,%2,%3}, [%4];"
        : "=r"(r[0]), "=r"(r[1]), "=r"(r[2]), "=r"(r[3]) : "r"(addr));
}
__device__ __forceinline__ void ldsm2t(uint32_t* r, uint32_t addr) {
    asm volatile("ldmatrix.sync.aligned.m8n8.x2.trans.shared.b16 {%0,%1}, [%2];"
        : "=r"(r[0]), "=r"(r[1]) : "r"(addr));
}
__device__ __forceinline__ void mma16816(float* c, const uint32_t* a, const uint32_t* b) {
    asm volatile("mma.sync.aligned.m16n8k16.row.col.f32.bf16.bf16.f32 "
        "{%0,%1,%2,%3}, {%4,%5,%6,%7}, {%8,%9}, {%0,%1,%2,%3};"
        : "+f"(c[0]), "+f"(c[1]), "+f"(c[2]), "+f"(c[3])
        : "r"(a[0]), "r"(a[1]), "r"(a[2]), "r"(a[3]), "r"(b[0]), "r"(b[1]));
}

// ===========================================================================
// Kernel A: q = X @ Wt ; t = X @ Wx^T + bh ; also split V=X into bf16 hi/lo.
// 512 threads = 16 rows x 32 units; grid 128 = one full wave.
// ===========================================================================
__global__ __launch_bounds__(512) void proj_kernel(
    const float* __restrict__ inputs, const float* __restrict__ Wt,
    const float* __restrict__ Wx, const float* __restrict__ bh)
{
    extern __shared__ float4 s_w[];            // [0:2048) Wt4, [2048:4096) Wx4
    float4* s_wt4 = s_w;
    float4* s_wx4 = s_w + 2048;
    for (int i = threadIdx.x; i < 64 * 32; i += 512) {
        const int d4 = i >> 5, u = i & 31;
        s_wt4[i] = make_float4(Wt[(4*d4+0)*UU + u], Wt[(4*d4+1)*UU + u],
                               Wt[(4*d4+2)*UU + u], Wt[(4*d4+3)*UU + u]);
        s_wx4[i] = ((const float4*)(Wx + u * DD))[d4];
    }
    __syncthreads();

    const int warp = threadIdx.x >> 5;     // local row 0..15
    const int u    = threadIdx.x & 31;
    const int row  = blockIdx.x * 16 + warp;
    const float4* xr = (const float4*)(inputs + (size_t)row * DD);

    // V hi/lo split: this thread handles d = u*8 .. u*8+7 of its row
    {
        const float4 xa = xr[u * 2], xb = xr[u * 2 + 1];
        const float v[8] = {xa.x, xa.y, xa.z, xa.w, xb.x, xb.y, xb.z, xb.w};
        __nv_bfloat16 hbuf[8], lbuf[8];
        #pragma unroll
        for (int j = 0; j < 8; j++) {
            const __nv_bfloat16 h = __float2bfloat16(v[j]);
            hbuf[j] = h;
            lbuf[j] = __float2bfloat16(v[j] - __bfloat162float(h));
        }
        *(uint4*)(g_vh + (size_t)row * DD + u * 8) = *(const uint4*)hbuf;
        *(uint4*)(g_vl + (size_t)row * DD + u * 8) = *(const uint4*)lbuf;
    }

    float accq = 0.0f, acck = 0.0f;
    #pragma unroll 8
    for (int d4 = 0; d4 < 64; d4++) {
        const float4 x  = xr[d4];
        const float4 wt = s_wt4[d4 * 32 + u];
        const float4 wx = s_wx4[d4 * 32 + u];
        accq = fmaf(x.x, wt.x, accq); accq = fmaf(x.y, wt.y, accq);
        accq = fmaf(x.z, wt.z, accq); accq = fmaf(x.w, wt.w, accq);
        acck = fmaf(x.x, wx.x, acck); acck = fmaf(x.y, wx.y, acck);
        acck = fmaf(x.z, wx.z, acck); acck = fmaf(x.w, wx.w, acck);
    }
    g_q[row * UU + u] = accq;
    g_t[row * UU + u] = acck + bh[u];
}

// ===========================================================================
// Kernel B: alpha in REGISTERS (32/lane), softmax via shfl, store P hi/lo.
// Warp = query; lane's k set = { i*32 + lane : i in 0..31 }.
// ===========================================================================
__global__ __launch_bounds__(256) void alpha_kernel(
    const float* __restrict__ Wa, const float* __restrict__ ba)
{
    __shared__ float s_t[KC][UU + 4];     // 9216 B, 144B row stride: x4-conflict-free
    __shared__ float s_q[QPB][UU];
    __shared__ float s_wa[UU];

    const int b    = blockIdx.x / (LL / QPB);
    const int q0   = (blockIdx.x % (LL / QPB)) * QPB;
    const int tid  = threadIdx.x;
    const int warp = tid >> 5;
    const int lane = tid & 31;

    s_q[warp][lane] = g_q[((size_t)b * LL + q0 + warp) * UU + lane];
    if (tid < UU) s_wa[tid] = Wa[tid];
    const float bav = ba[0];
    __syncthreads();

    float areg[32];                        // alpha for k = i*32 + lane
    const float4* q4  = (const float4*)&s_q[warp][0];
    const float4* wa4 = (const float4*)&s_wa[0];

    #pragma unroll
    for (int c = 0; c < LL / KC; c++) {
        const float4* gt4 = (const float4*)(g_t + ((size_t)b * LL + c * KC) * UU);
        for (int i = tid; i < KC * 8; i += 256)
            ((float4*)&s_t[i >> 3][0])[i & 7] = gt4[i];
        __syncthreads();
        #pragma unroll
        for (int j = 0; j < KC / 32; j++) {
            const int kl = j * 32 + lane;
            const float4* t4 = (const float4*)&s_t[kl][0];
            float a0 = 0.f, a1 = 0.f, a2 = 0.f, a3 = 0.f;
            #pragma unroll
            for (int u4 = 0; u4 < 8; u4++) {
                const float4 qv = q4[u4];
                const float4 tv = t4[u4];
                const float4 wv = wa4[u4];
                a0 = fmaf(htanh(qv.x + tv.x), wv.x, a0);
                a1 = fmaf(htanh(qv.y + tv.y), wv.y, a1);
                a2 = fmaf(htanh(qv.z + tv.z), wv.z, a2);
                a3 = fmaf(htanh(qv.w + tv.w), wv.w, a3);
            }
            areg[c * 2 + j] = bav + ((a0 + a1) + (a2 + a3));
        }
        __syncthreads();
    }

    // ---- softmax entirely in registers + shfl ----
    float lmax = areg[0];
    #pragma unroll
    for (int i = 1; i < 32; i++) lmax = fmaxf(lmax, areg[i]);
    #pragma unroll
    for (int off = 16; off; off >>= 1)
        lmax = fmaxf(lmax, __shfl_xor_sync(0xffffffffu, lmax, off));

    float lsum = 0.0f;
    #pragma unroll
    for (int i = 0; i < 32; i++) {
        areg[i] = __expf(areg[i] - lmax);
        lsum += areg[i];
    }
    #pragma unroll
    for (int off = 16; off; off >>= 1)
        lsum += __shfl_xor_sync(0xffffffffu, lsum, off);
    const float inv = 1.0f / lsum;

    const size_t rowb = ((size_t)b * LL + q0 + warp) * LL;
    #pragma unroll
    for (int i = 0; i < 32; i++) {
        const float p = areg[i] * inv;
        const __nv_bfloat16 hi = __float2bfloat16(p);
        const __nv_bfloat16 lo = __float2bfloat16(p - __bfloat162float(hi));
        g_ph[rowb + i * 32 + lane] = hi;
        g_pl[rowb + i * 32 + lane] = lo;
    }
}

// ===========================================================================
// Kernel C: warp-MMA GEMM  C[64 q x 64 d] = P @ V (split bf16, fp32 acc),
// software-pipelined: chunk c+1 LDG overlaps chunk c MMAs.
// ===========================================================================
#define OFF_AH 0
#define OFF_AL (64*PITCH)
#define OFF_BH (2*64*PITCH)
#define OFF_BL (3*64*PITCH)
#define PV_SMEM_BYTES (4*64*PITCH*2)

__global__ __launch_bounds__(256) void pv_kernel(float* __restrict__ out)
{
    extern __shared__ __align__(16) __nv_bfloat16 sm[];
    const int tid    = threadIdx.x;
    const int wid    = tid >> 5;
    const int lane   = tid & 31;
    const int warp_m = wid >> 2;
    const int warp_n = wid & 3;
    const int q0g    = blockIdx.x * 64;
    const int b      = q0g >> 10;
    const int n0     = blockIdx.y * 64;
    const uint32_t smb = smem_u32(sm);

    // per-thread staging coords (4 A-vectors + 4 B-vectors per chunk)
    int a_plane[4], a_r[4], a_k8[4], b_plane[4], b_r[4], b_n8[4];
    uint32_t a_soff[4], b_soff[4];
    #pragma unroll
    for (int it = 0; it < 4; it++) {
        const int idx = tid + it * 256;
        a_plane[it] = idx >> 9;  a_r[it] = (idx >> 3) & 63;  a_k8[it] = (idx & 7) * 8;
        b_plane[it] = idx >> 9;  b_r[it] = (idx >> 3) & 63;  b_n8[it] = (idx & 7) * 8;
        a_soff[it] = (a_plane[it] ? OFF_AL : OFF_AH) + a_r[it] * PITCH + a_k8[it];
        b_soff[it] = (b_plane[it] ? OFF_BL : OFF_BH) + b_r[it] * PITCH + b_n8[it];
    }

    float acc[2][2][4];
    #pragma unroll
    for (int mt = 0; mt < 2; mt++)
        #pragma unroll
        for (int nt = 0; nt < 2; nt++)
            acc[mt][nt][0] = acc[mt][nt][1] = acc[mt][nt][2] = acc[mt][nt][3] = 0.f;

    uint4 pa[4], pb[4];
    // prefetch chunk 0
    #pragma unroll
    for (int it = 0; it < 4; it++) {
        const __nv_bfloat16* sa = a_plane[it] ? g_pl : g_ph;
        const __nv_bfloat16* sb = b_plane[it] ? g_vl : g_vh;
        pa[it] = *(const uint4*)(sa + (size_t)(q0g + a_r[it]) * LL + a_k8[it]);
        pb[it] = *(const uint4*)(sb + (size_t)(b * LL + b_r[it]) * DD + n0 + b_n8[it]);
    }

    #pragma unroll 1
    for (int c = 0; c < LL / KCH; c++) {
        // commit prefetched chunk to smem
        #pragma unroll
        for (int it = 0; it < 4; it++) {
            *(uint4*)(sm + a_soff[it]) = pa[it];
            *(uint4*)(sm + b_soff[it]) = pb[it];
        }
        __syncthreads();

        // issue next chunk's loads (overlap with MMAs below)
        if (c + 1 < LL / KCH) {
            const int kc1 = (c + 1) * KCH;
            #pragma unroll
            for (int it = 0; it < 4; it++) {
                const __nv_bfloat16* sa = a_plane[it] ? g_pl : g_ph;
                const __nv_bfloat16* sb = b_plane[it] ? g_vl : g_vh;
                pa[it] = *(const uint4*)(sa + (size_t)(q0g + a_r[it]) * LL + kc1 + a_k8[it]);
                pb[it] = *(const uint4*)(sb + (size_t)(b * LL + kc1 + b_r[it]) * DD + n0 + b_n8[it]);
            }
        }

        #pragma unroll
        for (int kk = 0; kk < KCH; kk += 16) {
            uint32_t ah[2][4], al[2][4], bh[2][2], bl[2][2];
            #pragma unroll
            for (int mt = 0; mt < 2; mt++) {
                const int row = warp_m * 32 + mt * 16 + (lane & 15);
                const int col = kk + (lane >> 4) * 8;
                ldsm4(ah[mt], smb + (uint32_t)(OFF_AH + row * PITCH + col) * 2);
                ldsm4(al[mt], smb + (uint32_t)(OFF_AL + row * PITCH + col) * 2);
            }
            #pragma unroll
            for (int nt = 0; nt < 2; nt++) {
                const int krow = kk + (lane & 15);
                const int col  = warp_n * 16 + nt * 8;
                ldsm2t(bh[nt], smb + (uint32_t)(OFF_BH + krow * PITCH + col) * 2);
                ldsm2t(bl[nt], smb + (uint32_t)(OFF_BL + krow * PITCH + col) * 2);
            }
            #pragma unroll
            for (int mt = 0; mt < 2; mt++)
                #pragma unroll
                for (int nt = 0; nt < 2; nt++) {
                    mma16816(acc[mt][nt], ah[mt], bh[nt]);   // Ph*Vh
                    mma16816(acc[mt][nt], ah[mt], bl[nt]);   // Ph*Vl
                    mma16816(acc[mt][nt], al[mt], bh[nt]);   // Pl*Vh
                }
        }
        __syncthreads();
    }

    #pragma unroll
    for (int mt = 0; mt < 2; mt++)
        #pragma unroll
        for (int nt = 0; nt < 2; nt++) {
            const int row = q0g + warp_m * 32 + mt * 16 + (lane >> 2);
            const int col = n0 + warp_n * 16 + nt * 8 + (lane & 3) * 2;
            float* o = out + (size_t)row * DD + col;
            o[0] = acc[mt][nt][0];
            o[1] = acc[mt][nt][1];
            o[8 * DD + 0] = acc[mt][nt][2];
            o[8 * DD + 1] = acc[mt][nt][3];
        }
}

// ===========================================================================
extern "C" void kernel_launch(void* const* d_in, const int* in_sizes, int n_in,
                              void* d_out, int out_size) {
    const float* inputs = (const float*)d_in[0];
    const float* Wt     = (const float*)d_in[1];
    const float* Wx     = (const float*)d_in[2];
    const float* bh     = (const float*)d_in[3];
    const float* Wa     = (const float*)d_in[4];
    const float* ba     = (const float*)d_in[5];
    float* out = (float*)d_out;

    cudaFuncSetAttribute(proj_kernel, cudaFuncAttributeMaxDynamicSharedMemorySize, 65536);
    cudaFuncSetAttribute(proj_kernel, cudaFuncAttributePreferredSharedMemoryCarveout, 100);
    cudaFuncSetAttribute(pv_kernel,   cudaFuncAttributePreferredSharedMemoryCarveout, 100);

    proj_kernel<<<BB * LL / 16, 512, 65536>>>(inputs, Wt, Wx, bh);
    alpha_kernel<<<BB * LL / QPB, 256>>>(Wa, ba);
    pv_kernel<<<dim3(BB * LL / 64, DD / 64), 256, PV_SMEM_BYTES>>>(out);
}

// round 8
// speedup vs baseline: 2.6280x; 1.0697x over previous
#include <cuda_runtime.h>
#include <cuda_bf16.h>
#include <cstdint>

#define BB  2
#define LL  1024
#define DD  256
#define UU  32
#define QPB 8
#define KC  64
#define KCH 64       // k-chunk for pv gemm
#define PITCH 72     // pv smem row pitch in bf16 (144B: conflict-free ldmatrix)

// ---- device scratch (no allocs allowed) ----
__device__ __align__(16) float g_q[BB*LL*UU];
__device__ __align__(16) float g_t[BB*LL*UU];
__device__ __align__(16) __nv_bfloat16 g_ph[BB*LL*LL];   // P hi (normalized)
__device__ __align__(16) __nv_bfloat16 g_pl[BB*LL*LL];   // P lo
__device__ __align__(16) __nv_bfloat16 g_vh[BB*LL*DD];   // V hi  [b][k][d]
__device__ __align__(16) __nv_bfloat16 g_vl[BB*LL*DD];   // V lo

__device__ __forceinline__ float htanh(float x) {
    float y; asm("tanh.approx.f32 %0, %1;" : "=f"(y) : "f"(x)); return y;
}
__device__ __forceinline__ uint32_t smem_u32(const void* p) {
    uint32_t a;
    asm("{ .reg .u64 t; cvta.to.shared.u64 t, %1; cvt.u32.u64 %0, t; }" : "=r"(a) : "l"(p));
    return a;
}
__device__ __forceinline__ void ldsm4(uint32_t* r, uint32_t addr) {
    asm volatile("ldmatrix.sync.aligned.m8n8.x4.shared.b16 {%0,%1,%2,%3}, [%4];"
        : "=r"(r[0]), "=r"(r[1]), "=r"(r[2]), "=r"(r[3]) : "r"(addr));
}
__device__ __forceinline__ void ldsm2t(uint32_t* r, uint32_t addr) {
    asm volatile("ldmatrix.sync.aligned.m8n8.x2.trans.shared.b16 {%0,%1}, [%2];"
        : "=r"(r[0]), "=r"(r[1]) : "r"(addr));
}
__device__ __forceinline__ void mma16816(float* c, const uint32_t* a, const uint32_t* b) {
    asm volatile("mma.sync.aligned.m16n8k16.row.col.f32.bf16.bf16.f32 "
        "{%0,%1,%2,%3}, {%4,%5,%6,%7}, {%8,%9}, {%0,%1,%2,%3};"
        : "+f"(c[0]), "+f"(c[1]), "+f"(c[2]), "+f"(c[3])
        : "r"(a[0]), "r"(a[1]), "r"(a[2]), "r"(a[3]), "r"(b[0]), "r"(b[1]));
}
__device__ __forceinline__ void split_bf16(float v, __nv_bfloat16& h, __nv_bfloat16& l) {
    h = __float2bfloat16(v);
    l = __float2bfloat16(v - __bfloat162float(h));
}

// ===========================================================================
// Kernel A (MMA): [q | t] = X @ [Wt | Wx^T]  via split-bf16 HMMA.
// Also writes X hi/lo to g_vh/g_vl (the V operand for pv_kernel).
// Grid 32 CTAs x 256 thr; per-CTA: M=64 rows, N=64 (32 q + 32 t), K=256.
// ===========================================================================
#define APITCH 264                    // 64 x 264 bf16 per plane (528B rows)
#define BPITCH 72                     // 256 x 72 bf16 per plane
#define PA_H 0
#define PA_L (64*APITCH)
#define PB_H (2*64*APITCH)
#define PB_L (PB_H + 256*BPITCH)
#define PROJ_SMEM ((PB_L + 256*BPITCH) * 2)   // bytes

__global__ __launch_bounds__(256) void proj_mma_kernel(
    const float* __restrict__ inputs, const float* __restrict__ Wt,
    const float* __restrict__ Wx, const float* __restrict__ bh)
{
    extern __shared__ __align__(16) __nv_bfloat16 sm[];
    const int tid  = threadIdx.x;
    const int wid  = tid >> 5;
    const int lane = tid & 31;
    const int row0 = blockIdx.x * 64;
    const uint32_t smb = smem_u32(sm);

    // ---- stage A = X tile [64 x 256] hi/lo; also write g_vh/g_vl ----
    for (int idx = tid; idx < 64 * 64; idx += 256) {
        const int r  = idx >> 6;
        const int c4 = idx & 63;
        const float4 x = *(const float4*)(inputs + (size_t)(row0 + r) * DD + c4 * 4);
        __nv_bfloat16 h[4], l[4];
        split_bf16(x.x, h[0], l[0]); split_bf16(x.y, h[1], l[1]);
        split_bf16(x.z, h[2], l[2]); split_bf16(x.w, h[3], l[3]);
        *(uint2*)(sm + PA_H + r * APITCH + c4 * 4) = *(const uint2*)h;
        *(uint2*)(sm + PA_L + r * APITCH + c4 * 4) = *(const uint2*)l;
        *(uint2*)(g_vh + (size_t)(row0 + r) * DD + c4 * 4) = *(const uint2*)h;
        *(uint2*)(g_vl + (size_t)(row0 + r) * DD + c4 * 4) = *(const uint2*)l;
    }
    // ---- stage B[k][n]: n<32 -> Wt[k][n] ; n>=32 -> Wx[n-32][k] ----
    for (int idx = tid; idx < 256 * 8; idx += 256) {   // Wt, coalesced
        const int k = idx >> 3, n4 = idx & 7;
        const float4 w = *(const float4*)(Wt + k * UU + n4 * 4);
        __nv_bfloat16 h[4], l[4];
        split_bf16(w.x, h[0], l[0]); split_bf16(w.y, h[1], l[1]);
        split_bf16(w.z, h[2], l[2]); split_bf16(w.w, h[3], l[3]);
        *(uint2*)(sm + PB_H + k * BPITCH + n4 * 4) = *(const uint2*)h;
        *(uint2*)(sm + PB_L + k * BPITCH + n4 * 4) = *(const uint2*)l;
    }
    for (int idx = tid; idx < 32 * 64; idx += 256) {   // Wx, transposed store
        const int n = idx >> 6, k4 = idx & 63;
        const float4 w = *(const float4*)(Wx + n * DD + k4 * 4);
        __nv_bfloat16 h[4], l[4];
        split_bf16(w.x, h[0], l[0]); split_bf16(w.y, h[1], l[1]);
        split_bf16(w.z, h[2], l[2]); split_bf16(w.w, h[3], l[3]);
        #pragma unroll
        for (int j = 0; j < 4; j++) {
            sm[PB_H + (k4 * 4 + j) * BPITCH + 32 + n] = h[j];
            sm[PB_L + (k4 * 4 + j) * BPITCH + 32 + n] = l[j];
        }
    }
    __syncthreads();

    // ---- MMA: 8 warps = 2 warp_m x 4 warp_n; warp tile 32m x 16n ----
    const int warp_m = wid >> 2;
    const int warp_n = wid & 3;
    float acc[2][2][4];
    #pragma unroll
    for (int mt = 0; mt < 2; mt++)
        #pragma unroll
        for (int nt = 0; nt < 2; nt++)
            acc[mt][nt][0] = acc[mt][nt][1] = acc[mt][nt][2] = acc[mt][nt][3] = 0.f;

    #pragma unroll
    for (int kk = 0; kk < 256; kk += 16) {
        uint32_t ah[2][4], al[2][4], bhf[2][2], blf[2][2];
        #pragma unroll
        for (int mt = 0; mt < 2; mt++) {
            const int r = warp_m * 32 + mt * 16 + (lane & 15);
            const int c = kk + (lane >> 4) * 8;
            ldsm4(ah[mt], smb + (uint32_t)(PA_H + r * APITCH + c) * 2);
            ldsm4(al[mt], smb + (uint32_t)(PA_L + r * APITCH + c) * 2);
        }
        #pragma unroll
        for (int nt = 0; nt < 2; nt++) {
            const int kr = kk + (lane & 15);
            const int c  = warp_n * 16 + nt * 8;
            ldsm2t(bhf[nt], smb + (uint32_t)(PB_H + kr * BPITCH + c) * 2);
            ldsm2t(blf[nt], smb + (uint32_t)(PB_L + kr * BPITCH + c) * 2);
        }
        #pragma unroll
        for (int mt = 0; mt < 2; mt++)
            #pragma unroll
            for (int nt = 0; nt < 2; nt++) {
                mma16816(acc[mt][nt], ah[mt], bhf[nt]);
                mma16816(acc[mt][nt], ah[mt], blf[nt]);
                mma16816(acc[mt][nt], al[mt], bhf[nt]);
            }
    }

    // ---- epilogue: col<32 -> g_q ; col>=32 -> g_t + bh ----
    #pragma unroll
    for (int mt = 0; mt < 2; mt++)
        #pragma unroll
        for (int nt = 0; nt < 2; nt++) {
            const int r0 = row0 + warp_m * 32 + mt * 16 + (lane >> 2);
            const int c  = warp_n * 16 + nt * 8 + (lane & 3) * 2;
            #pragma unroll
            for (int half = 0; half < 2; half++) {
                const int r = r0 + half * 8;
                const float v0 = acc[mt][nt][half * 2 + 0];
                const float v1 = acc[mt][nt][half * 2 + 1];
                if (c < 32) {
                    g_q[r * UU + c]     = v0;
                    g_q[r * UU + c + 1] = v1;
                } else {
                    g_t[r * UU + c - 32] = v0 + __ldg(bh + c - 32);
                    g_t[r * UU + c - 31] = v1 + __ldg(bh + c - 31);
                }
            }
        }
}

// ===========================================================================
// Kernel B: alpha in REGISTERS (32/lane), softmax via shfl, store P hi/lo.
// ===========================================================================
__global__ __launch_bounds__(256) void alpha_kernel(
    const float* __restrict__ Wa, const float* __restrict__ ba)
{
    __shared__ float s_t[KC][UU + 4];
    __shared__ float s_q[QPB][UU];
    __shared__ float s_wa[UU];

    const int b    = blockIdx.x / (LL / QPB);
    const int q0   = (blockIdx.x % (LL / QPB)) * QPB;
    const int tid  = threadIdx.x;
    const int warp = tid >> 5;
    const int lane = tid & 31;

    s_q[warp][lane] = g_q[((size_t)b * LL + q0 + warp) * UU + lane];
    if (tid < UU) s_wa[tid] = Wa[tid];
    const float bav = ba[0];
    __syncthreads();

    float areg[32];
    const float4* q4  = (const float4*)&s_q[warp][0];
    const float4* wa4 = (const float4*)&s_wa[0];

    #pragma unroll
    for (int c = 0; c < LL / KC; c++) {
        const float4* gt4 = (const float4*)(g_t + ((size_t)b * LL + c * KC) * UU);
        for (int i = tid; i < KC * 8; i += 256)
            ((float4*)&s_t[i >> 3][0])[i & 7] = gt4[i];
        __syncthreads();
        #pragma unroll
        for (int j = 0; j < KC / 32; j++) {
            const int kl = j * 32 + lane;
            const float4* t4 = (const float4*)&s_t[kl][0];
            float a0 = 0.f, a1 = 0.f, a2 = 0.f, a3 = 0.f;
            #pragma unroll
            for (int u4 = 0; u4 < 8; u4++) {
                const float4 qv = q4[u4];
                const float4 tv = t4[u4];
                const float4 wv = wa4[u4];
                a0 = fmaf(htanh(qv.x + tv.x), wv.x, a0);
                a1 = fmaf(htanh(qv.y + tv.y), wv.y, a1);
                a2 = fmaf(htanh(qv.z + tv.z), wv.z, a2);
                a3 = fmaf(htanh(qv.w + tv.w), wv.w, a3);
            }
            areg[c * 2 + j] = bav + ((a0 + a1) + (a2 + a3));
        }
        __syncthreads();
    }

    float lmax = areg[0];
    #pragma unroll
    for (int i = 1; i < 32; i++) lmax = fmaxf(lmax, areg[i]);
    #pragma unroll
    for (int off = 16; off; off >>= 1)
        lmax = fmaxf(lmax, __shfl_xor_sync(0xffffffffu, lmax, off));

    float lsum = 0.0f;
    #pragma unroll
    for (int i = 0; i < 32; i++) {
        areg[i] = __expf(areg[i] - lmax);
        lsum += areg[i];
    }
    #pragma unroll
    for (int off = 16; off; off >>= 1)
        lsum += __shfl_xor_sync(0xffffffffu, lsum, off);
    const float inv = 1.0f / lsum;

    const size_t rowb = ((size_t)b * LL + q0 + warp) * LL;
    #pragma unroll
    for (int i = 0; i < 32; i++) {
        const float p = areg[i] * inv;
        const __nv_bfloat16 hi = __float2bfloat16(p);
        const __nv_bfloat16 lo = __float2bfloat16(p - __bfloat162float(hi));
        g_ph[rowb + i * 32 + lane] = hi;
        g_pl[rowb + i * 32 + lane] = lo;
    }
}

// ===========================================================================
// Kernel C: warp-MMA GEMM  C[64 q x 64 d] = P @ V (split bf16, fp32 acc),
// software-pipelined: chunk c+1 LDG overlaps chunk c MMAs.
// ===========================================================================
#define OFF_AH 0
#define OFF_AL (64*PITCH)
#define OFF_BH (2*64*PITCH)
#define OFF_BL (3*64*PITCH)
#define PV_SMEM_BYTES (4*64*PITCH*2)

__global__ __launch_bounds__(256) void pv_kernel(float* __restrict__ out)
{
    extern __shared__ __align__(16) __nv_bfloat16 sm[];
    const int tid    = threadIdx.x;
    const int wid    = tid >> 5;
    const int lane   = tid & 31;
    const int warp_m = wid >> 2;
    const int warp_n = wid & 3;
    const int q0g    = blockIdx.x * 64;
    const int b      = q0g >> 10;
    const int n0     = blockIdx.y * 64;
    const uint32_t smb = smem_u32(sm);

    int a_plane[4], a_r[4], a_k8[4], b_plane[4], b_r[4], b_n8[4];
    uint32_t a_soff[4], b_soff[4];
    #pragma unroll
    for (int it = 0; it < 4; it++) {
        const int idx = tid + it * 256;
        a_plane[it] = idx >> 9;  a_r[it] = (idx >> 3) & 63;  a_k8[it] = (idx & 7) * 8;
        b_plane[it] = idx >> 9;  b_r[it] = (idx >> 3) & 63;  b_n8[it] = (idx & 7) * 8;
        a_soff[it] = (a_plane[it] ? OFF_AL : OFF_AH) + a_r[it] * PITCH + a_k8[it];
        b_soff[it] = (b_plane[it] ? OFF_BL : OFF_BH) + b_r[it] * PITCH + b_n8[it];
    }

    float acc[2][2][4];
    #pragma unroll
    for (int mt = 0; mt < 2; mt++)
        #pragma unroll
        for (int nt = 0; nt < 2; nt++)
            acc[mt][nt][0] = acc[mt][nt][1] = acc[mt][nt][2] = acc[mt][nt][3] = 0.f;

    uint4 pa[4], pb[4];
    #pragma unroll
    for (int it = 0; it < 4; it++) {
        const __nv_bfloat16* sa = a_plane[it] ? g_pl : g_ph;
        const __nv_bfloat16* sb = b_plane[it] ? g_vl : g_vh;
        pa[it] = *(const uint4*)(sa + (size_t)(q0g + a_r[it]) * LL + a_k8[it]);
        pb[it] = *(const uint4*)(sb + (size_t)(b * LL + b_r[it]) * DD + n0 + b_n8[it]);
    }

    #pragma unroll 1
    for (int c = 0; c < LL / KCH; c++) {
        #pragma unroll
        for (int it = 0; it < 4; it++) {
            *(uint4*)(sm + a_soff[it]) = pa[it];
            *(uint4*)(sm + b_soff[it]) = pb[it];
        }
        __syncthreads();

        if (c + 1 < LL / KCH) {
            const int kc1 = (c + 1) * KCH;
            #pragma unroll
            for (int it = 0; it < 4; it++) {
                const __nv_bfloat16* sa = a_plane[it] ? g_pl : g_ph;
                const __nv_bfloat16* sb = b_plane[it] ? g_vl : g_vh;
                pa[it] = *(const uint4*)(sa + (size_t)(q0g + a_r[it]) * LL + kc1 + a_k8[it]);
                pb[it] = *(const uint4*)(sb + (size_t)(b * LL + kc1 + b_r[it]) * DD + n0 + b_n8[it]);
            }
        }

        #pragma unroll
        for (int kk = 0; kk < KCH; kk += 16) {
            uint32_t ah[2][4], al[2][4], bh[2][2], bl[2][2];
            #pragma unroll
            for (int mt = 0; mt < 2; mt++) {
                const int row = warp_m * 32 + mt * 16 + (lane & 15);
                const int col = kk + (lane >> 4) * 8;
                ldsm4(ah[mt], smb + (uint32_t)(OFF_AH + row * PITCH + col) * 2);
                ldsm4(al[mt], smb + (uint32_t)(OFF_AL + row * PITCH + col) * 2);
            }
            #pragma unroll
            for (int nt = 0; nt < 2; nt++) {
                const int krow = kk + (lane & 15);
                const int col  = warp_n * 16 + nt * 8;
                ldsm2t(bh[nt], smb + (uint32_t)(OFF_BH + krow * PITCH + col) * 2);
                ldsm2t(bl[nt], smb + (uint32_t)(OFF_BL + krow * PITCH + col) * 2);
            }
            #pragma unroll
            for (int mt = 0; mt < 2; mt++)
                #pragma unroll
                for (int nt = 0; nt < 2; nt++) {
                    mma16816(acc[mt][nt], ah[mt], bh[nt]);
                    mma16816(acc[mt][nt], ah[mt], bl[nt]);
                    mma16816(acc[mt][nt], al[mt], bh[nt]);
                }
        }
        __syncthreads();
    }

    #pragma unroll
    for (int mt = 0; mt < 2; mt++)
        #pragma unroll
        for (int nt = 0; nt < 2; nt++) {
            const int row = q0g + warp_m * 32 + mt * 16 + (lane >> 2);
            const int col = n0 + warp_n * 16 + nt * 8 + (lane & 3) * 2;
            float* o = out + (size_t)row * DD + col;
            o[0] = acc[mt][nt][0];
            o[1] = acc[mt][nt][1];
            o[8 * DD + 0] = acc[mt][nt][2];
            o[8 * DD + 1] = acc[mt][nt][3];
        }
}

// ===========================================================================
extern "C" void kernel_launch(void* const* d_in, const int* in_sizes, int n_in,
                              void* d_out, int out_size) {
    const float* inputs = (const float*)d_in[0];
    const float* Wt     = (const float*)d_in[1];
    const float* Wx     = (const float*)d_in[2];
    const float* bh     = (const float*)d_in[3];
    const float* Wa     = (const float*)d_in[4];
    const float* ba     = (const float*)d_in[5];
    float* out = (float*)d_out;

    cudaFuncSetAttribute(proj_mma_kernel, cudaFuncAttributeMaxDynamicSharedMemorySize, PROJ_SMEM);
    cudaFuncSetAttribute(pv_kernel, cudaFuncAttributePreferredSharedMemoryCarveout, 100);

    proj_mma_kernel<<<BB * LL / 64, 256, PROJ_SMEM>>>(inputs, Wt, Wx, bh);
    alpha_kernel<<<BB * LL / QPB, 256>>>(Wa, ba);
    pv_kernel<<<dim3(BB * LL / 64, DD / 64), 256, PV_SMEM_BYTES>>>(out);
}

// round 10
// speedup vs baseline: 2.8946x; 1.1014x over previous
#include <cuda_runtime.h>
#include <cuda_bf16.h>
#include <cstdint>

#define BB  2
#define LL  1024
#define DD  256
#define UU  32
#define QPB 8
#define KC  64
#define KCH 64       // k-chunk for pv gemm
#define PITCH 72     // smem row pitch in bf16 (144B: conflict-free ldmatrix)

// ---- device scratch (no allocs allowed) ----
__device__ __align__(16) float g_q[BB*LL*UU];
__device__ __align__(16) float g_t[BB*LL*UU];
__device__ __align__(16) __nv_bfloat16 g_ph[BB*LL*LL];   // P hi (normalized)
__device__ __align__(16) __nv_bfloat16 g_pl[BB*LL*LL];   // P lo
__device__ __align__(16) __nv_bfloat16 g_vh[BB*LL*DD];   // V hi  [b][k][d]
__device__ __align__(16) __nv_bfloat16 g_vl[BB*LL*DD];   // V lo
__device__ __align__(16) __nv_bfloat16 g_wbh[DD*64];     // W stacked [k][n] hi (n<32:Wt, n>=32:Wx^T)
__device__ __align__(16) __nv_bfloat16 g_wbl[DD*64];     // W stacked lo

__device__ __forceinline__ float htanh(float x) {
    float y; asm("tanh.approx.f32 %0, %1;" : "=f"(y) : "f"(x)); return y;
}
__device__ __forceinline__ uint32_t smem_u32(const void* p) {
    uint32_t a;
    asm("{ .reg .u64 t; cvta.to.shared.u64 t, %1; cvt.u32.u64 %0, t; }" : "=r"(a) : "l"(p));
    return a;
}
__device__ __forceinline__ void ldsm4(uint32_t* r, uint32_t addr) {
    asm volatile("ldmatrix.sync.aligned.m8n8.x4.shared.b16 {%0,%1,%2,%3}, [%4];"
        : "=r"(r[0]), "=r"(r[1]), "=r"(r[2]), "=r"(r[3]) : "r"(addr));
}
__device__ __forceinline__ void ldsm2t(uint32_t* r, uint32_t addr) {
    asm volatile("ldmatrix.sync.aligned.m8n8.x2.trans.shared.b16 {%0,%1}, [%2];"
        : "=r"(r[0]), "=r"(r[1]) : "r"(addr));
}
__device__ __forceinline__ void mma16816(float* c, const uint32_t* a, const uint32_t* b) {
    asm volatile("mma.sync.aligned.m16n8k16.row.col.f32.bf16.bf16.f32 "
        "{%0,%1,%2,%3}, {%4,%5,%6,%7}, {%8,%9}, {%0,%1,%2,%3};"
        : "+f"(c[0]), "+f"(c[1]), "+f"(c[2]), "+f"(c[3])
        : "r"(a[0]), "r"(a[1]), "r"(a[2]), "r"(a[3]), "r"(b[0]), "r"(b[1]));
}
__device__ __forceinline__ void split_bf16(float v, __nv_bfloat16& h, __nv_bfloat16& l) {
    h = __float2bfloat16(v);
    l = __float2bfloat16(v - __bfloat162float(h));
}

// ===========================================================================
// Kernel W: one-time split of [Wt | Wx^T] into bf16 hi/lo, [k][64] layout.
// ===========================================================================
__global__ __launch_bounds__(256) void wsplit_kernel(
    const float* __restrict__ Wt, const float* __restrict__ Wx)
{
    const int base = blockIdx.x * 1024;
    for (int i = 0; i < 4; i++) {
        const int idx = base + i * 256 + threadIdx.x;  // k*64 + n
        const int k = idx >> 6, n = idx & 63;
        const float v = (n < UU) ? Wt[k * UU + n] : Wx[(n - UU) * DD + k];
        __nv_bfloat16 h, l;
        split_bf16(v, h, l);
        g_wbh[idx] = h;
        g_wbl[idx] = l;
    }
}

// ===========================================================================
// Kernel A (MMA): [q | t] = X @ [Wt | Wx^T], split-bf16 HMMA, M-tile 16.
// Grid 128 CTAs (full wave). Also writes X hi/lo to g_vh/g_vl.
// ===========================================================================
#define APITCH 264
#define PA_H 0
#define PA_L (16*APITCH)
#define PB_H (2*16*APITCH)
#define PB_L (PB_H + 256*PITCH)
#define PROJ_SMEM ((PB_L + 256*PITCH) * 2)

__global__ __launch_bounds__(256) void proj_mma_kernel(
    const float* __restrict__ inputs, const float* __restrict__ bh)
{
    extern __shared__ __align__(16) __nv_bfloat16 sm[];
    const int tid  = threadIdx.x;
    const int wid  = tid >> 5;
    const int lane = tid & 31;
    const int row0 = blockIdx.x * 16;
    const uint32_t smb = smem_u32(sm);

    // ---- stage A = X tile [16 x 256] hi/lo; also write g_vh/g_vl ----
    for (int idx = tid; idx < 16 * 64; idx += 256) {
        const int r  = idx >> 6;
        const int c4 = idx & 63;
        const float4 x = *(const float4*)(inputs + (size_t)(row0 + r) * DD + c4 * 4);
        __nv_bfloat16 h[4], l[4];
        split_bf16(x.x, h[0], l[0]); split_bf16(x.y, h[1], l[1]);
        split_bf16(x.z, h[2], l[2]); split_bf16(x.w, h[3], l[3]);
        *(uint2*)(sm + PA_H + r * APITCH + c4 * 4) = *(const uint2*)h;
        *(uint2*)(sm + PA_L + r * APITCH + c4 * 4) = *(const uint2*)l;
        *(uint2*)(g_vh + (size_t)(row0 + r) * DD + c4 * 4) = *(const uint2*)h;
        *(uint2*)(g_vl + (size_t)(row0 + r) * DD + c4 * 4) = *(const uint2*)l;
    }
    // ---- stage B = pre-split W [256 x 64] hi/lo (pure uint4 copies) ----
    for (int idx = tid; idx < 256 * 8 * 2; idx += 256) {
        const int plane = idx >> 11;
        const int k  = (idx >> 3) & 255;
        const int n8 = (idx & 7) * 8;
        const __nv_bfloat16* src = plane ? g_wbl : g_wbh;
        const uint4 v = *(const uint4*)(src + k * 64 + n8);
        *(uint4*)(sm + (plane ? PB_L : PB_H) + k * PITCH + n8) = v;
    }
    __syncthreads();

    // ---- MMA: 8 warps = 8 n-slices of 8 cols; warp tile 16m x 8n ----
    float acc[4] = {0.f, 0.f, 0.f, 0.f};
    #pragma unroll
    for (int kk = 0; kk < 256; kk += 16) {
        uint32_t ah[4], al[4], bhf[2], blf[2];
        {
            const int r = lane & 15;
            const int c = kk + (lane >> 4) * 8;
            ldsm4(ah, smb + (uint32_t)(PA_H + r * APITCH + c) * 2);
            ldsm4(al, smb + (uint32_t)(PA_L + r * APITCH + c) * 2);
        }
        {
            const int kr = kk + (lane & 15);
            const int c  = wid * 8;
            ldsm2t(bhf, smb + (uint32_t)(PB_H + kr * PITCH + c) * 2);
            ldsm2t(blf, smb + (uint32_t)(PB_L + kr * PITCH + c) * 2);
        }
        mma16816(acc, ah, bhf);
        mma16816(acc, ah, blf);
        mma16816(acc, al, bhf);
    }

    // ---- epilogue: col<32 -> g_q ; col>=32 -> g_t + bh ----
    #pragma unroll
    for (int half = 0; half < 2; half++) {
        const int r = row0 + (lane >> 2) + half * 8;
        const int c = wid * 8 + (lane & 3) * 2;
        const float v0 = acc[half * 2 + 0];
        const float v1 = acc[half * 2 + 1];
        if (c < UU) {
            g_q[r * UU + c]     = v0;
            g_q[r * UU + c + 1] = v1;
        } else {
            g_t[r * UU + c - 32] = v0 + __ldg(bh + c - 32);
            g_t[r * UU + c - 31] = v1 + __ldg(bh + c - 31);
        }
    }
}

// ===========================================================================
// Kernel B: alpha in REGISTERS (32/lane), softmax via shfl, store P hi/lo.
// ===========================================================================
__global__ __launch_bounds__(256) void alpha_kernel(
    const float* __restrict__ Wa, const float* __restrict__ ba)
{
    __shared__ float s_t[KC][UU + 4];
    __shared__ float s_q[QPB][UU];
    __shared__ float s_wa[UU];

    const int b    = blockIdx.x / (LL / QPB);
    const int q0   = (blockIdx.x % (LL / QPB)) * QPB;
    const int tid  = threadIdx.x;
    const int warp = tid >> 5;
    const int lane = tid & 31;

    s_q[warp][lane] = g_q[((size_t)b * LL + q0 + warp) * UU + lane];
    if (tid < UU) s_wa[tid] = Wa[tid];
    const float bav = ba[0];
    __syncthreads();

    float areg[32];
    const float4* q4  = (const float4*)&s_q[warp][0];
    const float4* wa4 = (const float4*)&s_wa[0];

    #pragma unroll
    for (int c = 0; c < LL / KC; c++) {
        const float4* gt4 = (const float4*)(g_t + ((size_t)b * LL + c * KC) * UU);
        for (int i = tid; i < KC * 8; i += 256)
            ((float4*)&s_t[i >> 3][0])[i & 7] = gt4[i];
        __syncthreads();
        #pragma unroll
        for (int j = 0; j < KC / 32; j++) {
            const int kl = j * 32 + lane;
            const float4* t4 = (const float4*)&s_t[kl][0];
            float a0 = 0.f, a1 = 0.f, a2 = 0.f, a3 = 0.f;
            #pragma unroll
            for (int u4 = 0; u4 < 8; u4++) {
                const float4 qv = q4[u4];
                const float4 tv = t4[u4];
                const float4 wv = wa4[u4];
                a0 = fmaf(htanh(qv.x + tv.x), wv.x, a0);
                a1 = fmaf(htanh(qv.y + tv.y), wv.y, a1);
                a2 = fmaf(htanh(qv.z + tv.z), wv.z, a2);
                a3 = fmaf(htanh(qv.w + tv.w), wv.w, a3);
            }
            areg[c * 2 + j] = bav + ((a0 + a1) + (a2 + a3));
        }
        __syncthreads();
    }

    float lmax = areg[0];
    #pragma unroll
    for (int i = 1; i < 32; i++) lmax = fmaxf(lmax, areg[i]);
    #pragma unroll
    for (int off = 16; off; off >>= 1)
        lmax = fmaxf(lmax, __shfl_xor_sync(0xffffffffu, lmax, off));

    float lsum = 0.0f;
    #pragma unroll
    for (int i = 0; i < 32; i++) {
        areg[i] = __expf(areg[i] - lmax);
        lsum += areg[i];
    }
    #pragma unroll
    for (int off = 16; off; off >>= 1)
        lsum += __shfl_xor_sync(0xffffffffu, lsum, off);
    const float inv = 1.0f / lsum;

    const size_t rowb = ((size_t)b * LL + q0 + warp) * LL;
    #pragma unroll
    for (int i = 0; i < 32; i++) {
        const float p = areg[i] * inv;
        const __nv_bfloat16 hi = __float2bfloat16(p);
        const __nv_bfloat16 lo = __float2bfloat16(p - __bfloat162float(hi));
        g_ph[rowb + i * 32 + lane] = hi;
        g_pl[rowb + i * 32 + lane] = lo;
    }
}

// ===========================================================================
// Kernel C: warp-MMA GEMM  C[64 q x 64 d] = P @ V (split bf16, fp32 acc),
// software-pipelined: chunk c+1 LDG overlaps chunk c MMAs.
// ===========================================================================
#define OFF_AH 0
#define OFF_AL (64*PITCH)
#define OFF_BH (2*64*PITCH)
#define OFF_BL (3*64*PITCH)
#define PV_SMEM_BYTES (4*64*PITCH*2)

__global__ __launch_bounds__(256) void pv_kernel(float* __restrict__ out)
{
    extern __shared__ __align__(16) __nv_bfloat16 sm[];
    const int tid    = threadIdx.x;
    const int wid    = tid >> 5;
    const int lane   = tid & 31;
    const int warp_m = wid >> 2;
    const int warp_n = wid & 3;
    const int q0g    = blockIdx.x * 64;
    const int b      = q0g >> 10;
    const int n0     = blockIdx.y * 64;
    const uint32_t smb = smem_u32(sm);

    int a_plane[4], a_r[4], a_k8[4], b_plane[4], b_r[4], b_n8[4];
    uint32_t a_soff[4], b_soff[4];
    #pragma unroll
    for (int it = 0; it < 4; it++) {
        const int idx = tid + it * 256;
        a_plane[it] = idx >> 9;  a_r[it] = (idx >> 3) & 63;  a_k8[it] = (idx & 7) * 8;
        b_plane[it] = idx >> 9;  b_r[it] = (idx >> 3) & 63;  b_n8[it] = (idx & 7) * 8;
        a_soff[it] = (a_plane[it] ? OFF_AL : OFF_AH) + a_r[it] * PITCH + a_k8[it];
        b_soff[it] = (b_plane[it] ? OFF_BL : OFF_BH) + b_r[it] * PITCH + b_n8[it];
    }

    float acc[2][2][4];
    #pragma unroll
    for (int mt = 0; mt < 2; mt++)
        #pragma unroll
        for (int nt = 0; nt < 2; nt++)
            acc[mt][nt][0] = acc[mt][nt][1] = acc[mt][nt][2] = acc[mt][nt][3] = 0.f;

    uint4 pa[4], pb[4];
    #pragma unroll
    for (int it = 0; it < 4; it++) {
        const __nv_bfloat16* sa = a_plane[it] ? g_pl : g_ph;
        const __nv_bfloat16* sb = b_plane[it] ? g_vl : g_vh;
        pa[it] = *(const uint4*)(sa + (size_t)(q0g + a_r[it]) * LL + a_k8[it]);
        pb[it] = *(const uint4*)(sb + (size_t)(b * LL + b_r[it]) * DD + n0 + b_n8[it]);
    }

    #pragma unroll 1
    for (int c = 0; c < LL / KCH; c++) {
        #pragma unroll
        for (int it = 0; it < 4; it++) {
            *(uint4*)(sm + a_soff[it]) = pa[it];
            *(uint4*)(sm + b_soff[it]) = pb[it];
        }
        __syncthreads();

        if (c + 1 < LL / KCH) {
            const int kc1 = (c + 1) * KCH;
            #pragma unroll
            for (int it = 0; it < 4; it++) {
                const __nv_bfloat16* sa = a_plane[it] ? g_pl : g_ph;
                const __nv_bfloat16* sb = b_plane[it] ? g_vl : g_vh;
                pa[it] = *(const uint4*)(sa + (size_t)(q0g + a_r[it]) * LL + kc1 + a_k8[it]);
                pb[it] = *(const uint4*)(sb + (size_t)(b * LL + kc1 + b_r[it]) * DD + n0 + b_n8[it]);
            }
        }

        #pragma unroll
        for (int kk = 0; kk < KCH; kk += 16) {
            uint32_t ah[2][4], al[2][4], bh[2][2], bl[2][2];
            #pragma unroll
            for (int mt = 0; mt < 2; mt++) {
                const int row = warp_m * 32 + mt * 16 + (lane & 15);
                const int col = kk + (lane >> 4) * 8;
                ldsm4(ah[mt], smb + (uint32_t)(OFF_AH + row * PITCH + col) * 2);
                ldsm4(al[mt], smb + (uint32_t)(OFF_AL + row * PITCH + col) * 2);
            }
            #pragma unroll
            for (int nt = 0; nt < 2; nt++) {
                const int krow = kk + (lane & 15);
                const int col  = warp_n * 16 + nt * 8;
                ldsm2t(bh[nt], smb + (uint32_t)(OFF_BH + krow * PITCH + col) * 2);
                ldsm2t(bl[nt], smb + (uint32_t)(OFF_BL + krow * PITCH + col) * 2);
            }
            #pragma unroll
            for (int mt = 0; mt < 2; mt++)
                #pragma unroll
                for (int nt = 0; nt < 2; nt++) {
                    mma16816(acc[mt][nt], ah[mt], bh[nt]);
                    mma16816(acc[mt][nt], ah[mt], bl[nt]);
                    mma16816(acc[mt][nt], al[mt], bh[nt]);
                }
        }
        __syncthreads();
    }

    #pragma unroll
    for (int mt = 0; mt < 2; mt++)
        #pragma unroll
        for (int nt = 0; nt < 2; nt++) {
            const int row = q0g + warp_m * 32 + mt * 16 + (lane >> 2);
            const int col = n0 + warp_n * 16 + nt * 8 + (lane & 3) * 2;
            float* o = out + (size_t)row * DD + col;
            o[0] = acc[mt][nt][0];
            o[1] = acc[mt][nt][1];
            o[8 * DD + 0] = acc[mt][nt][2];
            o[8 * DD + 1] = acc[mt][nt][3];
        }
}

// ===========================================================================
extern "C" void kernel_launch(void* const* d_in, const int* in_sizes, int n_in,
                              void* d_out, int out_size) {
    const float* inputs = (const float*)d_in[0];
    const float* Wt     = (const float*)d_in[1];
    const float* Wx     = (const float*)d_in[2];
    const float* bh     = (const float*)d_in[3];
    const float* Wa     = (const float*)d_in[4];
    const float* ba     = (const float*)d_in[5];
    float* out = (float*)d_out;

    cudaFuncSetAttribute(proj_mma_kernel, cudaFuncAttributeMaxDynamicSharedMemorySize, PROJ_SMEM);
    cudaFuncSetAttribute(pv_kernel, cudaFuncAttributePreferredSharedMemoryCarveout, 100);

    wsplit_kernel<<<16, 256>>>(Wt, Wx);
    proj_mma_kernel<<<BB * LL / 16, 256, PROJ_SMEM>>>(inputs, bh);
    alpha_kernel<<<BB * LL / QPB, 256>>>(Wa, ba);
    pv_kernel<<<dim3(BB * LL / 64, DD / 64), 256, PV_SMEM_BYTES>>>(out);
}

// round 11
// speedup vs baseline: 2.8962x; 1.0006x over previous
#include <cuda_runtime.h>
#include <cuda_bf16.h>
#include <cstdint>

#define BB  2
#define LL  1024
#define DD  256
#define UU  32
#define QPB 8
#define KC  64
#define KCH 64       // k-chunk for pv gemm
#define PITCH 72     // smem row pitch in bf16 (144B: conflict-free ldmatrix)

// ---- device scratch (no allocs allowed) ----
__device__ __align__(16) float g_q[BB*LL*UU];
__device__ __align__(16) float g_t[BB*LL*UU];
__device__ __align__(16) __nv_bfloat16 g_ph[BB*LL*LL];   // P hi (normalized)
__device__ __align__(16) __nv_bfloat16 g_pl[BB*LL*LL];   // P lo
__device__ __align__(16) __nv_bfloat16 g_vh[BB*LL*DD];   // V hi  [b][k][d]
__device__ __align__(16) __nv_bfloat16 g_vl[BB*LL*DD];   // V lo
__device__ __align__(16) __nv_bfloat16 g_wbh[DD*64];     // W stacked [k][n] hi
__device__ __align__(16) __nv_bfloat16 g_wbl[DD*64];     // W stacked lo

__device__ __forceinline__ float htanh(float x) {
    float y; asm("tanh.approx.f32 %0, %1;" : "=f"(y) : "f"(x)); return y;
}
__device__ __forceinline__ uint32_t smem_u32(const void* p) {
    uint32_t a;
    asm("{ .reg .u64 t; cvta.to.shared.u64 t, %1; cvt.u32.u64 %0, t; }" : "=r"(a) : "l"(p));
    return a;
}
__device__ __forceinline__ void ldsm4(uint32_t* r, uint32_t addr) {
    asm volatile("ldmatrix.sync.aligned.m8n8.x4.shared.b16 {%0,%1,%2,%3}, [%4];"
        : "=r"(r[0]), "=r"(r[1]), "=r"(r[2]), "=r"(r[3]) : "r"(addr));
}
__device__ __forceinline__ void ldsm2t(uint32_t* r, uint32_t addr) {
    asm volatile("ldmatrix.sync.aligned.m8n8.x2.trans.shared.b16 {%0,%1}, [%2];"
        : "=r"(r[0]), "=r"(r[1]) : "r"(addr));
}
__device__ __forceinline__ void mma16816(float* c, const uint32_t* a, const uint32_t* b) {
    asm volatile("mma.sync.aligned.m16n8k16.row.col.f32.bf16.bf16.f32 "
        "{%0,%1,%2,%3}, {%4,%5,%6,%7}, {%8,%9}, {%0,%1,%2,%3};"
        : "+f"(c[0]), "+f"(c[1]), "+f"(c[2]), "+f"(c[3])
        : "r"(a[0]), "r"(a[1]), "r"(a[2]), "r"(a[3]), "r"(b[0]), "r"(b[1]));
}
__device__ __forceinline__ void split_bf16(float v, __nv_bfloat16& h, __nv_bfloat16& l) {
    h = __float2bfloat16(v);
    l = __float2bfloat16(v - __bfloat162float(h));
}
__device__ __forceinline__ void cpasync16(uint32_t saddr, const void* gptr) {
    asm volatile("cp.async.cg.shared.global [%0], [%1], 16;" :: "r"(saddr), "l"(gptr));
}
__device__ __forceinline__ void cpasync_commit() {
    asm volatile("cp.async.commit_group;");
}
__device__ __forceinline__ void cpasync_wait0() {
    asm volatile("cp.async.wait_group 0;");
}

// ===========================================================================
// Kernel W: one-time split of [Wt | Wx^T] into bf16 hi/lo, [k][64] layout.
// ===========================================================================
__global__ __launch_bounds__(256) void wsplit_kernel(
    const float* __restrict__ Wt, const float* __restrict__ Wx)
{
    const int base = blockIdx.x * 1024;
    for (int i = 0; i < 4; i++) {
        const int idx = base + i * 256 + threadIdx.x;
        const int k = idx >> 6, n = idx & 63;
        const float v = (n < UU) ? Wt[k * UU + n] : Wx[(n - UU) * DD + k];
        __nv_bfloat16 h, l;
        split_bf16(v, h, l);
        g_wbh[idx] = h;
        g_wbl[idx] = l;
    }
}

// ===========================================================================
// Kernel A (MMA): [q | t] = X @ [Wt | Wx^T], split-bf16 HMMA, M-tile 16.
// ===========================================================================
#define APITCH 264
#define PA_H 0
#define PA_L (16*APITCH)
#define PB_H (2*16*APITCH)
#define PB_L (PB_H + 256*PITCH)
#define PROJ_SMEM ((PB_L + 256*PITCH) * 2)

__global__ __launch_bounds__(256) void proj_mma_kernel(
    const float* __restrict__ inputs, const float* __restrict__ bh)
{
    extern __shared__ __align__(16) __nv_bfloat16 sm[];
    const int tid  = threadIdx.x;
    const int wid  = tid >> 5;
    const int lane = tid & 31;
    const int row0 = blockIdx.x * 16;
    const uint32_t smb = smem_u32(sm);

    for (int idx = tid; idx < 16 * 64; idx += 256) {
        const int r  = idx >> 6;
        const int c4 = idx & 63;
        const float4 x = *(const float4*)(inputs + (size_t)(row0 + r) * DD + c4 * 4);
        __nv_bfloat16 h[4], l[4];
        split_bf16(x.x, h[0], l[0]); split_bf16(x.y, h[1], l[1]);
        split_bf16(x.z, h[2], l[2]); split_bf16(x.w, h[3], l[3]);
        *(uint2*)(sm + PA_H + r * APITCH + c4 * 4) = *(const uint2*)h;
        *(uint2*)(sm + PA_L + r * APITCH + c4 * 4) = *(const uint2*)l;
        *(uint2*)(g_vh + (size_t)(row0 + r) * DD + c4 * 4) = *(const uint2*)h;
        *(uint2*)(g_vl + (size_t)(row0 + r) * DD + c4 * 4) = *(const uint2*)l;
    }
    for (int idx = tid; idx < 256 * 8 * 2; idx += 256) {
        const int plane = idx >> 11;
        const int k  = (idx >> 3) & 255;
        const int n8 = (idx & 7) * 8;
        const __nv_bfloat16* src = plane ? g_wbl : g_wbh;
        const uint4 v = *(const uint4*)(src + k * 64 + n8);
        *(uint4*)(sm + (plane ? PB_L : PB_H) + k * PITCH + n8) = v;
    }
    __syncthreads();

    float acc[4] = {0.f, 0.f, 0.f, 0.f};
    #pragma unroll
    for (int kk = 0; kk < 256; kk += 16) {
        uint32_t ah[4], al[4], bhf[2], blf[2];
        {
            const int r = lane & 15;
            const int c = kk + (lane >> 4) * 8;
            ldsm4(ah, smb + (uint32_t)(PA_H + r * APITCH + c) * 2);
            ldsm4(al, smb + (uint32_t)(PA_L + r * APITCH + c) * 2);
        }
        {
            const int kr = kk + (lane & 15);
            const int c  = wid * 8;
            ldsm2t(bhf, smb + (uint32_t)(PB_H + kr * PITCH + c) * 2);
            ldsm2t(blf, smb + (uint32_t)(PB_L + kr * PITCH + c) * 2);
        }
        mma16816(acc, ah, bhf);
        mma16816(acc, ah, blf);
        mma16816(acc, al, bhf);
    }

    #pragma unroll
    for (int half = 0; half < 2; half++) {
        const int r = row0 + (lane >> 2) + half * 8;
        const int c = wid * 8 + (lane & 3) * 2;
        const float v0 = acc[half * 2 + 0];
        const float v1 = acc[half * 2 + 1];
        if (c < UU) {
            g_q[r * UU + c]     = v0;
            g_q[r * UU + c + 1] = v1;
        } else {
            g_t[r * UU + c - 32] = v0 + __ldg(bh + c - 32);
            g_t[r * UU + c - 31] = v1 + __ldg(bh + c - 31);
        }
    }
}

// ===========================================================================
// Kernel B: alpha in REGISTERS (32/lane), softmax via shfl, store P hi/lo.
// ===========================================================================
__global__ __launch_bounds__(256) void alpha_kernel(
    const float* __restrict__ Wa, const float* __restrict__ ba)
{
    __shared__ float s_t[KC][UU + 4];
    __shared__ float s_q[QPB][UU];
    __shared__ float s_wa[UU];

    const int b    = blockIdx.x / (LL / QPB);
    const int q0   = (blockIdx.x % (LL / QPB)) * QPB;
    const int tid  = threadIdx.x;
    const int warp = tid >> 5;
    const int lane = tid & 31;

    s_q[warp][lane] = g_q[((size_t)b * LL + q0 + warp) * UU + lane];
    if (tid < UU) s_wa[tid] = Wa[tid];
    const float bav = ba[0];
    __syncthreads();

    float areg[32];
    const float4* q4  = (const float4*)&s_q[warp][0];
    const float4* wa4 = (const float4*)&s_wa[0];

    #pragma unroll
    for (int c = 0; c < LL / KC; c++) {
        const float4* gt4 = (const float4*)(g_t + ((size_t)b * LL + c * KC) * UU);
        for (int i = tid; i < KC * 8; i += 256)
            ((float4*)&s_t[i >> 3][0])[i & 7] = gt4[i];
        __syncthreads();
        #pragma unroll
        for (int j = 0; j < KC / 32; j++) {
            const int kl = j * 32 + lane;
            const float4* t4 = (const float4*)&s_t[kl][0];
            float a0 = 0.f, a1 = 0.f, a2 = 0.f, a3 = 0.f;
            #pragma unroll
            for (int u4 = 0; u4 < 8; u4++) {
                const float4 qv = q4[u4];
                const float4 tv = t4[u4];
                const float4 wv = wa4[u4];
                a0 = fmaf(htanh(qv.x + tv.x), wv.x, a0);
                a1 = fmaf(htanh(qv.y + tv.y), wv.y, a1);
                a2 = fmaf(htanh(qv.z + tv.z), wv.z, a2);
                a3 = fmaf(htanh(qv.w + tv.w), wv.w, a3);
            }
            areg[c * 2 + j] = bav + ((a0 + a1) + (a2 + a3));
        }
        __syncthreads();
    }

    float lmax = areg[0];
    #pragma unroll
    for (int i = 1; i < 32; i++) lmax = fmaxf(lmax, areg[i]);
    #pragma unroll
    for (int off = 16; off; off >>= 1)
        lmax = fmaxf(lmax, __shfl_xor_sync(0xffffffffu, lmax, off));

    float lsum = 0.0f;
    #pragma unroll
    for (int i = 0; i < 32; i++) {
        areg[i] = __expf(areg[i] - lmax);
        lsum += areg[i];
    }
    #pragma unroll
    for (int off = 16; off; off >>= 1)
        lsum += __shfl_xor_sync(0xffffffffu, lsum, off);
    const float inv = 1.0f / lsum;

    const size_t rowb = ((size_t)b * LL + q0 + warp) * LL;
    #pragma unroll
    for (int i = 0; i < 32; i++) {
        const float p = areg[i] * inv;
        const __nv_bfloat16 hi = __float2bfloat16(p);
        const __nv_bfloat16 lo = __float2bfloat16(p - __bfloat162float(hi));
        g_ph[rowb + i * 32 + lane] = hi;
        g_pl[rowb + i * 32 + lane] = lo;
    }
}

// ===========================================================================
// Kernel C: warp-MMA GEMM  C[32 q x 64 d] = P @ V (split bf16, fp32 acc).
// cp.async double-buffered; grid (64, 4) = 256 CTAs for 2-3 CTAs/SM.
// Stage layout (bf16 units): [AH 32xP][AL 32xP][BH 64xP][BL 64xP]
// ===========================================================================
#define S_AH 0
#define S_AL (32*PITCH)
#define S_BH (2*32*PITCH)
#define S_BL (S_BH + 64*PITCH)
#define STAGE_ELE (S_BL + 64*PITCH)          // 13824 bf16 per stage
#define PV_SMEM_BYTES (2*STAGE_ELE*2)        // 55296 B

__global__ __launch_bounds__(256) void pv_kernel(float* __restrict__ out)
{
    extern __shared__ __align__(16) __nv_bfloat16 sm[];
    const int tid    = threadIdx.x;
    const int wid    = tid >> 5;
    const int lane   = tid & 31;
    const int warp_m = wid >> 2;       // 0..1 (16 rows each)
    const int warp_n = wid & 3;        // 0..3 (16 cols each)
    const int q0g    = blockIdx.x * 32;
    const int b      = q0g >> 10;
    const int n0     = blockIdx.y * 64;
    const uint32_t smb = smem_u32(sm);

    // per-thread staging slots: 6 x 16B per stage (A: 512 vecs, B: 1024 vecs)
    int s_kind[6];                 // 0=A, 1=B
    const __nv_bfloat16* s_src[6]; // plane base
    int s_r[6], s_o8[6];           // row, 8-elem offset
    uint32_t s_soff[6];            // smem offset within stage (bf16 units)
    #pragma unroll
    for (int it = 0; it < 6; it++) {
        const int i = tid + it * 256;        // 0..1535
        if (i < 512) {
            const int plane = i >> 8;        // 0=hi,1=lo
            s_kind[it] = 0;
            s_src[it]  = plane ? g_pl : g_ph;
            s_r[it]    = (i >> 3) & 31;
            s_o8[it]   = (i & 7) * 8;
            s_soff[it] = (plane ? S_AL : S_AH) + s_r[it] * PITCH + s_o8[it];
        } else {
            const int j = i - 512;
            const int plane = j >> 9;
            s_kind[it] = 1;
            s_src[it]  = plane ? g_vl : g_vh;
            s_r[it]    = (j >> 3) & 63;
            s_o8[it]   = (j & 7) * 8;
            s_soff[it] = (plane ? S_BL : S_BH) + s_r[it] * PITCH + s_o8[it];
        }
    }

    // issue one stage's cp.asyncs for k-chunk kc0 into stage buffer st
    auto issue_stage = [&](int kc0, int st) {
        const uint32_t sb = smb + (uint32_t)(st * STAGE_ELE) * 2;
        #pragma unroll
        for (int it = 0; it < 6; it++) {
            const void* g = (s_kind[it] == 0)
                ? (const void*)(s_src[it] + (size_t)(q0g + s_r[it]) * LL + kc0 + s_o8[it])
                : (const void*)(s_src[it] + (size_t)(b * LL + kc0 + s_r[it]) * DD + n0 + s_o8[it]);
            cpasync16(sb + s_soff[it] * 2, g);
        }
        cpasync_commit();
    };

    float acc[2][4];
    #pragma unroll
    for (int nt = 0; nt < 2; nt++)
        acc[nt][0] = acc[nt][1] = acc[nt][2] = acc[nt][3] = 0.f;

    issue_stage(0, 0);

    #pragma unroll 1
    for (int c = 0; c < LL / KCH; c++) {
        cpasync_wait0();             // stage c resident
        __syncthreads();
        if (c + 1 < LL / KCH)
            issue_stage((c + 1) * KCH, (c + 1) & 1);   // overlaps MMAs below

        const uint32_t st = smb + (uint32_t)((c & 1) * STAGE_ELE) * 2;
        #pragma unroll
        for (int kk = 0; kk < KCH; kk += 16) {
            uint32_t ah[4], al[4], bh[2][2], bl[2][2];
            {
                const int r = warp_m * 16 + (lane & 15);
                const int col = kk + (lane >> 4) * 8;
                ldsm4(ah, st + (uint32_t)(S_AH + r * PITCH + col) * 2);
                ldsm4(al, st + (uint32_t)(S_AL + r * PITCH + col) * 2);
            }
            #pragma unroll
            for (int nt = 0; nt < 2; nt++) {
                const int kr  = kk + (lane & 15);
                const int col = warp_n * 16 + nt * 8;
                ldsm2t(bh[nt], st + (uint32_t)(S_BH + kr * PITCH + col) * 2);
                ldsm2t(bl[nt], st + (uint32_t)(S_BL + kr * PITCH + col) * 2);
            }
            #pragma unroll
            for (int nt = 0; nt < 2; nt++) {
                mma16816(acc[nt], ah, bh[nt]);
                mma16816(acc[nt], ah, bl[nt]);
                mma16816(acc[nt], al, bh[nt]);
            }
        }
        __syncthreads();             // all MMAs done before stage c+2 overwrites
    }

    #pragma unroll
    for (int nt = 0; nt < 2; nt++) {
        const int row = q0g + warp_m * 16 + (lane >> 2);
        const int col = n0 + warp_n * 16 + nt * 8 + (lane & 3) * 2;
        float* o = out + (size_t)row * DD + col;
        o[0] = acc[nt][0];
        o[1] = acc[nt][1];
        o[8 * DD + 0] = acc[nt][2];
        o[8 * DD + 1] = acc[nt][3];
    }
}

// ===========================================================================
extern "C" void kernel_launch(void* const* d_in, const int* in_sizes, int n_in,
                              void* d_out, int out_size) {
    const float* inputs = (const float*)d_in[0];
    const float* Wt     = (const float*)d_in[1];
    const float* Wx     = (const float*)d_in[2];
    const float* bh     = (const float*)d_in[3];
    const float* Wa     = (const float*)d_in[4];
    const float* ba     = (const float*)d_in[5];
    float* out = (float*)d_out;

    cudaFuncSetAttribute(proj_mma_kernel, cudaFuncAttributeMaxDynamicSharedMemorySize, PROJ_SMEM);
    cudaFuncSetAttribute(pv_kernel, cudaFuncAttributeMaxDynamicSharedMemorySize, PV_SMEM_BYTES);
    cudaFuncSetAttribute(pv_kernel, cudaFuncAttributePreferredSharedMemoryCarveout, 100);

    wsplit_kernel<<<16, 256>>>(Wt, Wx);
    proj_mma_kernel<<<BB * LL / 16, 256, PROJ_SMEM>>>(inputs, bh);
    alpha_kernel<<<BB * LL / QPB, 256>>>(Wa, ba);
    pv_kernel<<<dim3(BB * LL / 32, DD / 64), 256, PV_SMEM_BYTES>>>(out);
}